// round 1
// baseline (speedup 1.0000x reference)
#include <cuda_runtime.h>
#include <math.h>

// ---------------- problem constants ----------------
constexpr int kB = 8, kC = 64, kH = 256, kW = 256;
constexpr int kE = 512, kNH = 8, kHD = 64;
constexpr int kP = 16, kN = 15, kL = 225;      // n=15 windows, L=225 blocks/img
constexpr int kFV = 4096;                       // 16 ch-groups * 16 * 16
constexpr int kRows = kB * (kP + kL);           // 1928 rows through embedding
constexpr int kPatchRows = kB * kP;             // 128

// ---------------- device scratch (no allocations allowed) ----------------
__device__ float g_pooledF[kB * 16 * 128 * 128];   // pooled features (B,16,128,128)
__device__ float g_X[kRows * kFV];                 // pooled vectors: rows 0..127 patches, 128.. blocks
__device__ float g_Y[kRows * kE];                  // patch2vec output
__device__ float g_Yn[kRows * kE];                 // after LN (pe | be)
__device__ float g_QKV[kRows * 3 * kE];            // fused QKV
__device__ float g_attn[kPatchRows * kE];          // attention output
__device__ float g_proj[kPatchRows * kE];          // Wo projection
__device__ float g_res[kPatchRows * kE];           // LN(attn+pe)
__device__ float g_hid[kPatchRows * kE];           // MLP hidden
__device__ float g_xm[kPatchRows * kE];            // gelu(hid)+res
__device__ float g_outs[kPatchRows * 2];           // (B,16,2)
__device__ float g_sums[kB * 17 * 3];
__device__ float g_cnt[kB * 17];
__device__ float g_newv[kB * 17 * 3];              // newv_full (B,17,3)

// ---------------- pooling ----------------
// pooledF[b][cg][y][x] = mean over cc(4), 2x2 spatial of features
__global__ void pool_features_kernel(const float* __restrict__ f) {
    int i = blockIdx.x * blockDim.x + threadIdx.x;
    if (i >= kB * 16 * 128 * 128) return;
    int x = i & 127, y = (i >> 7) & 127, cg = (i >> 14) & 15, b = i >> 18;
    float s = 0.f;
#pragma unroll
    for (int cc = 0; cc < 4; cc++) {
        const float* base = f + ((size_t)(b * kC + cg * 4 + cc) * kH + 2 * y) * kW + 2 * x;
#pragma unroll
        for (int dy = 0; dy < 2; dy++) {
            float2 v = *(const float2*)(base + dy * kW);
            s += v.x + v.y;
        }
    }
    g_pooledF[i] = s * (1.f / 16.f);
}

// patches (B,P,C,32,32) -> X rows [0,128)
__global__ void pool_patches_kernel(const float* __restrict__ p) {
    int i = blockIdx.x * blockDim.x + threadIdx.x;
    if (i >= kPatchRows * kFV) return;
    int v = i & 4095, n = i >> 12;
    int ww = v & 15, hh = (v >> 4) & 15, cg = v >> 8;
    float s = 0.f;
#pragma unroll
    for (int cc = 0; cc < 4; cc++) {
        const float* base = p + (size_t)n * 65536 + (cg * 4 + cc) * 1024 + 2 * ww;
#pragma unroll
        for (int dh = 0; dh < 2; dh++) {
            float2 v2 = *(const float2*)(base + (2 * hh + dh) * 32);
            s += v2.x + v2.y;
        }
    }
    g_X[(size_t)n * kFV + v] = s * (1.f / 16.f);
}

// gather block pooled vectors from pooledF -> X rows [128,1928)
__global__ void gather_blocks_kernel() {
    int i = blockIdx.x * blockDim.x + threadIdx.x;
    if (i >= kB * kL * kFV) return;
    int v = i & 4095, r = i >> 12;
    int b = r / kL, l = r - b * kL;
    int li = l / kN, lj = l - li * kN;
    int ww = v & 15, hh = (v >> 4) & 15, cg = v >> 8;
    g_X[(size_t)(kPatchRows + r) * kFV + v] =
        g_pooledF[((size_t)(b * 16 + cg) * 128 + (8 * li + hh)) * 128 + 8 * lj + ww];
}

// ---------------- generic GEMM: C[M,N] = A[M,K] @ Bw[N,K]^T + bias ----------------
__global__ void gemm_bias_kernel(const float* __restrict__ A, const float* __restrict__ Bw,
                                 const float* __restrict__ bias, float* __restrict__ Cm,
                                 int M, int N, int K) {
    constexpr int BM = 128, BN = 64, BK = 8;
    __shared__ float As[BK][BM];
    __shared__ float Bs[BK][BN];
    int tid = threadIdx.x;                   // 256 threads
    int m0 = blockIdx.y * BM, n0 = blockIdx.x * BN;
    int arow = tid >> 1, acol = (tid & 1) * 4;   // A tile: 128x8, float4 each
    int brow = tid >> 2, bcol = (tid & 3) * 2;   // B tile: 64x8,  float2 each
    int tx = tid & 15, ty = tid >> 4;            // micro: 8 rows x 4 cols
    float acc[8][4];
#pragma unroll
    for (int i = 0; i < 8; i++)
#pragma unroll
        for (int j = 0; j < 4; j++) acc[i][j] = 0.f;

    const int gm = m0 + arow;
    const float* Aptr = A + (size_t)gm * K + acol;
    const float* Bptr = Bw + (size_t)(n0 + brow) * K + bcol;

    for (int k0 = 0; k0 < K; k0 += BK) {
        float4 av = make_float4(0.f, 0.f, 0.f, 0.f);
        if (gm < M) av = *(const float4*)(Aptr + k0);
        As[acol + 0][arow] = av.x;
        As[acol + 1][arow] = av.y;
        As[acol + 2][arow] = av.z;
        As[acol + 3][arow] = av.w;
        float2 bv = *(const float2*)(Bptr + k0);
        Bs[bcol + 0][brow] = bv.x;
        Bs[bcol + 1][brow] = bv.y;
        __syncthreads();
#pragma unroll
        for (int k = 0; k < BK; k++) {
            float ra[8], rb[4];
#pragma unroll
            for (int i = 0; i < 8; i++) ra[i] = As[k][ty * 8 + i];
#pragma unroll
            for (int j = 0; j < 4; j++) rb[j] = Bs[k][tx * 4 + j];
#pragma unroll
            for (int i = 0; i < 8; i++)
#pragma unroll
                for (int j = 0; j < 4; j++) acc[i][j] += ra[i] * rb[j];
        }
        __syncthreads();
    }
    float bj[4];
#pragma unroll
    for (int j = 0; j < 4; j++) bj[j] = bias[n0 + tx * 4 + j];
#pragma unroll
    for (int i = 0; i < 8; i++) {
        int gr = m0 + ty * 8 + i;
        if (gr < M) {
            float4 o = make_float4(acc[i][0] + bj[0], acc[i][1] + bj[1],
                                   acc[i][2] + bj[2], acc[i][3] + bj[3]);
            *(float4*)(Cm + (size_t)gr * N + n0 + tx * 4) = o;
        }
    }
}

// ---------------- layernorm (512 cols, optional residual) ----------------
__device__ __forceinline__ float block_reduce_sum(float v, float* sh) {
    int lane = threadIdx.x & 31, warp = threadIdx.x >> 5;
#pragma unroll
    for (int o = 16; o; o >>= 1) v += __shfl_xor_sync(0xffffffffu, v, o);
    if (lane == 0) sh[warp] = v;
    __syncthreads();
    if (warp == 0) {
        float t = (lane < 8) ? sh[lane] : 0.f;
#pragma unroll
        for (int o = 4; o; o >>= 1) t += __shfl_xor_sync(0xffffffffu, t, o);
        if (lane == 0) sh[0] = t;
    }
    __syncthreads();
    float r = sh[0];
    __syncthreads();
    return r;
}

__global__ void ln_kernel(const float* __restrict__ in, const float* __restrict__ resid,
                          const float* __restrict__ g, const float* __restrict__ bb,
                          float* __restrict__ out) {
    __shared__ float sh[32];
    int row = blockIdx.x, tid = threadIdx.x;  // 256 threads, 2 elems/thread
    size_t base = (size_t)row * 512;
    float x0 = in[base + tid], x1 = in[base + 256 + tid];
    if (resid) { x0 += resid[base + tid]; x1 += resid[base + 256 + tid]; }
    float mu = block_reduce_sum(x0 + x1, sh) * (1.f / 512.f);
    float d0 = x0 - mu, d1 = x1 - mu;
    float var = block_reduce_sum(d0 * d0 + d1 * d1, sh) * (1.f / 512.f);
    float rstd = rsqrtf(var + 1e-5f);
    out[base + tid]       = d0 * rstd * g[tid] + bb[tid];
    out[base + 256 + tid] = d1 * rstd * g[tid + 256] + bb[tid + 256];
}

// ---------------- attention: 16 queries x 225 keys x 64, one block per (b,h) ----------------
__global__ void attn_kernel() {
    __shared__ float qs[16 * 64];
    __shared__ float sc[16][228];
    int bh = blockIdx.x;
    int b = bh >> 3, h = bh & 7;
    int tid = threadIdx.x;  // 256
    for (int i = tid; i < 1024; i += 256)
        qs[i] = g_QKV[(size_t)(b * 16 + (i >> 6)) * 1536 + h * 64 + (i & 63)];
    __syncthreads();
    for (int idx = tid; idx < 16 * 225; idx += 256) {
        int p = idx / 225, l = idx - p * 225;
        const float* kr = g_QKV + (size_t)(kPatchRows + b * kL + l) * 1536 + 512 + h * 64;
        float s = 0.f;
#pragma unroll
        for (int d = 0; d < 64; d++) s += qs[p * 64 + d] * kr[d];
        sc[p][l] = s * 0.125f;  // 1/sqrt(64)
    }
    __syncthreads();
    int warp = tid >> 5, lane = tid & 31;
    for (int p = warp; p < 16; p += 8) {
        float mx = -1e30f;
        for (int l = lane; l < 225; l += 32) mx = fmaxf(mx, sc[p][l]);
#pragma unroll
        for (int o = 16; o; o >>= 1) mx = fmaxf(mx, __shfl_xor_sync(0xffffffffu, mx, o));
        float sum = 0.f;
        for (int l = lane; l < 225; l += 32) { float e = __expf(sc[p][l] - mx); sc[p][l] = e; sum += e; }
#pragma unroll
        for (int o = 16; o; o >>= 1) sum += __shfl_xor_sync(0xffffffffu, sum, o);
        float inv = 1.f / sum;
        for (int l = lane; l < 225; l += 32) sc[p][l] *= inv;
    }
    __syncthreads();
    for (int i = tid; i < 1024; i += 256) {
        int p = i >> 6, d = i & 63;
        const float* vbase = g_QKV + (size_t)(kPatchRows + b * kL) * 1536 + 1024 + h * 64 + d;
        float s = 0.f;
        for (int l = 0; l < 225; l++) s += sc[p][l] * vbase[(size_t)l * 1536];
        g_attn[(size_t)(b * 16 + p) * 512 + h * 64 + d] = s;
    }
}

// ---------------- MLP epilogue ----------------
__global__ void gelu_res_kernel() {
    int i = blockIdx.x * blockDim.x + threadIdx.x;
    if (i >= kPatchRows * kE) return;
    float hv = g_hid[i];
    g_xm[i] = 0.5f * hv * (1.f + erff(hv * 0.70710678118654752f)) + g_res[i];
}

__global__ void outs_kernel(const float* __restrict__ Wc, const float* __restrict__ bc) {
    int t = threadIdx.x;  // 256 = 128 rows x 2
    int row = t >> 1, j = t & 1;
    const float* x = g_xm + (size_t)row * 512;
    const float* w = Wc + j * 512;
    float s = 0.f;
    for (int k = 0; k < 512; k++) s += x[k] * w[k];
    g_outs[row * 2 + j] = s + bc[j];
}

// ---------------- segment mean + final scatter ----------------
__global__ void zero_seg_kernel() {
    int t = threadIdx.x;
    if (t < kB * 17 * 3) g_sums[t] = 0.f;
    if (t < kB * 17) g_cnt[t] = 0.f;
}

__global__ void seg_kernel(const float* __restrict__ probs, const int* __restrict__ masks) {
    __shared__ float ssum[51];
    __shared__ float scnt[17];
    int t = threadIdx.x;  // 256
    if (t < 51) ssum[t] = 0.f;
    if (t < 17) scnt[t] = 0.f;
    __syncthreads();
    int b = blockIdx.x >> 6;         // 64 blocks per image
    int chunk = blockIdx.x & 63;     // 1024 pixels per block
    int base = chunk * 1024;
#pragma unroll
    for (int k = 0; k < 4; k++) {
        int pix = base + k * 256 + t;
        int lab = masks[b * 65536 + pix];
        atomicAdd(&scnt[lab], 1.f);
#pragma unroll
        for (int c = 0; c < 3; c++)
            atomicAdd(&ssum[lab * 3 + c], probs[((size_t)(b * 3 + c)) * 65536 + pix]);
    }
    __syncthreads();
    if (t < 51) atomicAdd(&g_sums[b * 51 + t], ssum[t]);
    if (t < 17) atomicAdd(&g_cnt[b * 17 + t], scnt[t]);
}

__global__ void newv_kernel() {
    int t = threadIdx.x;  // 128
    if (t < 24) { int b = t / 3, c = t % 3; g_newv[b * 51 + c] = 0.f; }  // label 0 rows
    int b = t >> 4, p = t & 15, lab = p + 1;
    float denom = fmaxf(g_cnt[b * 17 + lab], 1.f);
    float m0 = g_sums[(b * 17 + lab) * 3 + 0] / denom + 1e-6f;
    float m1 = g_sums[(b * 17 + lab) * 3 + 1] / denom + 1e-6f;
    float m2 = g_sums[(b * 17 + lab) * 3 + 2] / denom + 1e-6f;
    float o0 = g_outs[(b * 16 + p) * 2 + 0], o1 = g_outs[(b * 16 + p) * 2 + 1];
    float n0 = m0 / (0.5f * (m1 + m2)) * (0.5f * (o0 + o1));
    g_newv[(b * 17 + lab) * 3 + 0] = n0;
    g_newv[(b * 17 + lab) * 3 + 1] = o0;
    g_newv[(b * 17 + lab) * 3 + 2] = o1;
}

__global__ void scatter_kernel(const float* __restrict__ probs, const int* __restrict__ masks,
                               float* __restrict__ out) {
    int i = blockIdx.x * blockDim.x + threadIdx.x;
    if (i >= kB * 65536) return;
    int b = i >> 16, pix = i & 65535;
    int lab = masks[i];
#pragma unroll
    for (int c = 0; c < 3; c++) {
        size_t o = ((size_t)(b * 3 + c)) * 65536 + pix;
        out[o] = (lab > 0) ? g_newv[(b * 17 + lab) * 3 + c] : probs[o];
    }
}

// ---------------- launch ----------------
extern "C" void kernel_launch(void* const* d_in, const int* /*in_sizes*/, int /*n_in*/,
                              void* d_out, int /*out_size*/) {
    const float* features = (const float*)d_in[0];
    const float* probs    = (const float*)d_in[1];
    const float* patches  = (const float*)d_in[2];
    const int*   masks    = (const int*)d_in[3];
    const float* ln_g = (const float*)d_in[4];
    const float* ln_b = (const float*)d_in[5];
    const float* Wr   = (const float*)d_in[6];
    const float* br   = (const float*)d_in[7];
    const float* Wqkv = (const float*)d_in[8];
    const float* bqkv = (const float*)d_in[9];
    const float* Wo   = (const float*)d_in[10];
    const float* bo   = (const float*)d_in[11];
    const float* Wm   = (const float*)d_in[12];
    const float* bm   = (const float*)d_in[13];
    const float* Wc   = (const float*)d_in[14];
    const float* bc   = (const float*)d_in[15];
    float* out = (float*)d_out;

    float *pX, *pY, *pYn, *pQKV, *pAttn, *pProj, *pRes, *pHid;
    cudaGetSymbolAddress((void**)&pX, g_X);
    cudaGetSymbolAddress((void**)&pY, g_Y);
    cudaGetSymbolAddress((void**)&pYn, g_Yn);
    cudaGetSymbolAddress((void**)&pQKV, g_QKV);
    cudaGetSymbolAddress((void**)&pAttn, g_attn);
    cudaGetSymbolAddress((void**)&pProj, g_proj);
    cudaGetSymbolAddress((void**)&pRes, g_res);
    cudaGetSymbolAddress((void**)&pHid, g_hid);

    pool_features_kernel<<<(kB * 16 * 128 * 128) / 256, 256>>>(features);
    pool_patches_kernel<<<(kPatchRows * kFV) / 256, 256>>>(patches);
    gather_blocks_kernel<<<(kB * kL * kFV) / 256, 256>>>();

    // patch2vec: (1928,4096)@(4096,512)^T
    gemm_bias_kernel<<<dim3(512 / 64, (kRows + 127) / 128), 256>>>(pX, Wr, br, pY, kRows, 512, 4096);
    ln_kernel<<<kRows, 256>>>(pY, nullptr, ln_g, ln_b, pYn);

    // fused QKV: (1928,512)@(512,1536)^T
    gemm_bias_kernel<<<dim3(1536 / 64, (kRows + 127) / 128), 256>>>(pYn, Wqkv, bqkv, pQKV, kRows, 1536, 512);
    attn_kernel<<<kB * kNH, 256>>>();

    // out proj + residual LN
    gemm_bias_kernel<<<dim3(512 / 64, 1), 256>>>(pAttn, Wo, bo, pProj, kPatchRows, 512, 512);
    ln_kernel<<<kPatchRows, 256>>>(pProj, pYn, ln_g, ln_b, pRes);

    // MLP
    gemm_bias_kernel<<<dim3(512 / 64, 1), 256>>>(pRes, Wm, bm, pHid, kPatchRows, 512, 512);
    gelu_res_kernel<<<(kPatchRows * kE) / 256, 256>>>();
    outs_kernel<<<1, 256>>>(Wc, bc);

    // segment statistics + final output
    zero_seg_kernel<<<1, 512>>>();
    seg_kernel<<<kB * 64, 256>>>(probs, masks);
    newv_kernel<<<1, 128>>>();
    scatter_kernel<<<(kB * 65536) / 256, 256>>>(probs, masks, out);
}

// round 3
// speedup vs baseline: 1.4624x; 1.4624x over previous
#include <cuda_runtime.h>
#include <math.h>
#include <stdint.h>

// ---------------- problem constants ----------------
constexpr int kB = 8, kC = 64, kH = 256, kW = 256;
constexpr int kE = 512, kNH = 8, kHD = 64;
constexpr int kP = 16, kN = 15, kL = 225;      // n=15 windows, L=225 blocks/img
constexpr int kFV = 4096;                       // 16 ch-groups * 16 * 16
constexpr int kRows = kB * (kP + kL);           // 1928 rows through embedding
constexpr int kPatchRows = kB * kP;             // 128

// ---------------- device scratch (no allocations allowed) ----------------
__device__ float g_pooledF[kB * 16 * 128 * 128];   // pooled features (B,16,128,128)
__device__ float g_X[kRows * kFV];                 // pooled vectors
__device__ float g_Y[kRows * kE];                  // patch2vec output
__device__ float g_Yn[kRows * kE];                 // after LN (pe | be)
__device__ float g_QKV[kRows * 3 * kE];            // fused QKV
__device__ float g_attn[kPatchRows * kE];
__device__ float g_proj[kPatchRows * kE];
__device__ float g_res[kPatchRows * kE];
__device__ float g_hid[kPatchRows * kE];
__device__ float g_xm[kPatchRows * kE];
__device__ float g_outs[kPatchRows * 2];
__device__ float g_sums[kB * 17 * 3];
__device__ float g_cnt[kB * 17];
__device__ float g_newv[kB * 17 * 3];

// ---------------- pooling ----------------
__global__ void pool_features_kernel(const float* __restrict__ f) {
    int i = blockIdx.x * blockDim.x + threadIdx.x;
    if (i >= kB * 16 * 128 * 128) return;
    int x = i & 127, y = (i >> 7) & 127, cg = (i >> 14) & 15, b = i >> 18;
    float s = 0.f;
#pragma unroll
    for (int cc = 0; cc < 4; cc++) {
        const float* base = f + ((size_t)(b * kC + cg * 4 + cc) * kH + 2 * y) * kW + 2 * x;
#pragma unroll
        for (int dy = 0; dy < 2; dy++) {
            float2 v = *(const float2*)(base + dy * kW);
            s += v.x + v.y;
        }
    }
    g_pooledF[i] = s * (1.f / 16.f);
}

__global__ void pool_patches_kernel(const float* __restrict__ p) {
    int i = blockIdx.x * blockDim.x + threadIdx.x;
    if (i >= kPatchRows * kFV) return;
    int v = i & 4095, n = i >> 12;
    int ww = v & 15, hh = (v >> 4) & 15, cg = v >> 8;
    float s = 0.f;
#pragma unroll
    for (int cc = 0; cc < 4; cc++) {
        const float* base = p + (size_t)n * 65536 + (cg * 4 + cc) * 1024 + 2 * ww;
#pragma unroll
        for (int dh = 0; dh < 2; dh++) {
            float2 v2 = *(const float2*)(base + (2 * hh + dh) * 32);
            s += v2.x + v2.y;
        }
    }
    g_X[(size_t)n * kFV + v] = s * (1.f / 16.f);
}

__global__ void gather_blocks_kernel() {
    int i = blockIdx.x * blockDim.x + threadIdx.x;
    if (i >= kB * kL * kFV) return;
    int v = i & 4095, r = i >> 12;
    int b = r / kL, l = r - b * kL;
    int li = l / kN, lj = l - li * kN;
    int ww = v & 15, hh = (v >> 4) & 15, cg = v >> 8;
    g_X[(size_t)(kPatchRows + r) * kFV + v] =
        g_pooledF[((size_t)(b * 16 + cg) * 128 + (8 * li + hh)) * 128 + 8 * lj + ww];
}

// ---------------- tensor-core GEMM (3xTF32): C[M,N] = A[M,K] @ Bw[N,K]^T + bias ----------------
__device__ __forceinline__ void split_tf32(float x, uint32_t& hi, uint32_t& lo) {
    asm("cvt.rna.tf32.f32 %0, %1;" : "=r"(hi) : "f"(x));
    float r = x - __uint_as_float(hi);
    asm("cvt.rna.tf32.f32 %0, %1;" : "=r"(lo) : "f"(r));
}

__device__ __forceinline__ void mma_tf32(float* d, const uint32_t* a, const uint32_t* b) {
    asm volatile(
        "mma.sync.aligned.m16n8k8.row.col.f32.tf32.tf32.f32 "
        "{%0,%1,%2,%3}, {%4,%5,%6,%7}, {%8,%9}, {%0,%1,%2,%3};"
        : "+f"(d[0]), "+f"(d[1]), "+f"(d[2]), "+f"(d[3])
        : "r"(a[0]), "r"(a[1]), "r"(a[2]), "r"(a[3]), "r"(b[0]), "r"(b[1]));
}

__device__ __forceinline__ void cp_async16(void* smem, const void* g, bool valid) {
    uint32_t s = (uint32_t)__cvta_generic_to_shared(smem);
    int sz = valid ? 16 : 0;
    asm volatile("cp.async.cg.shared.global [%0], [%1], 16, %2;\n" :: "r"(s), "l"(g), "r"(sz));
}
__device__ __forceinline__ void cp_async_commit() { asm volatile("cp.async.commit_group;\n" ::); }
template <int NN>
__device__ __forceinline__ void cp_async_wait() { asm volatile("cp.async.wait_group %0;\n" :: "n"(NN)); }

__global__ __launch_bounds__(256) void gemm_tc_kernel(
    const float* __restrict__ A, const float* __restrict__ Bw,
    const float* __restrict__ bias, float* __restrict__ Cm,
    int M, int N, int K)
{
    constexpr int BM = 128, BN = 64, BK = 16, PAD = 20;
    __shared__ float As[2][BM][PAD];
    __shared__ float Bs[2][BN][PAD];
    const int tid = threadIdx.x;
    const int lane = tid & 31, wid = tid >> 5;
    const int wm = wid >> 1, wn = wid & 1;      // 4 (m) x 2 (n) warps; each warp 32x32
    const int g = lane >> 2, t4 = lane & 3;
    const int m0 = blockIdx.y * BM, n0 = blockIdx.x * BN;

    float acc[2][4][4];
#pragma unroll
    for (int mt = 0; mt < 2; mt++)
#pragma unroll
        for (int nt = 0; nt < 4; nt++)
#pragma unroll
            for (int i = 0; i < 4; i++) acc[mt][nt][i] = 0.f;

    auto load_stage = [&](int buf, int kt) {
        int k0 = kt * BK;
#pragma unroll
        for (int i = 0; i < 2; i++) {
            int idx = tid + i * 256;
            int row = idx >> 2, kq = (idx & 3) * 4;
            bool v = (m0 + row) < M;
            const float* src = A + (size_t)(v ? (m0 + row) : 0) * K + k0 + kq;
            cp_async16(&As[buf][row][kq], src, v);
        }
        {
            int row = tid >> 2, kq = (tid & 3) * 4;
            const float* src = Bw + (size_t)(n0 + row) * K + k0 + kq;
            cp_async16(&Bs[buf][row][kq], src, true);
        }
        cp_async_commit();
    };

    auto compute = [&](int buf) {
#pragma unroll
        for (int ks = 0; ks < BK; ks += 8) {
            uint32_t ah[2][4], al[2][4], bh[4][2], bl[4][2];
#pragma unroll
            for (int mt = 0; mt < 2; mt++) {
                int mr = wm * 32 + mt * 16;
                split_tf32(As[buf][mr + g][ks + t4],         ah[mt][0], al[mt][0]);
                split_tf32(As[buf][mr + g + 8][ks + t4],     ah[mt][1], al[mt][1]);
                split_tf32(As[buf][mr + g][ks + t4 + 4],     ah[mt][2], al[mt][2]);
                split_tf32(As[buf][mr + g + 8][ks + t4 + 4], ah[mt][3], al[mt][3]);
            }
#pragma unroll
            for (int nt = 0; nt < 4; nt++) {
                int nr = wn * 32 + nt * 8 + g;
                split_tf32(Bs[buf][nr][ks + t4],     bh[nt][0], bl[nt][0]);
                split_tf32(Bs[buf][nr][ks + t4 + 4], bh[nt][1], bl[nt][1]);
            }
#pragma unroll
            for (int mt = 0; mt < 2; mt++)
#pragma unroll
                for (int nt = 0; nt < 4; nt++) {
                    mma_tf32(acc[mt][nt], al[mt], bh[nt]);
                    mma_tf32(acc[mt][nt], ah[mt], bl[nt]);
                    mma_tf32(acc[mt][nt], ah[mt], bh[nt]);
                }
        }
    };

    const int kTiles = K / BK;
    load_stage(0, 0);
    int buf = 0;
    for (int kt = 0; kt < kTiles; kt++) {
        // FIXED pipeline: commit next stage BEFORE waiting, so wait_group<1>
        // actually drains the oldest (current) stage.
        if (kt + 1 < kTiles) {
            load_stage(buf ^ 1, kt + 1);
            cp_async_wait<1>();
        } else {
            cp_async_wait<0>();
        }
        __syncthreads();
        compute(buf);
        __syncthreads();
        buf ^= 1;
    }

    // epilogue: bias + store
#pragma unroll
    for (int mt = 0; mt < 2; mt++) {
#pragma unroll
        for (int nt = 0; nt < 4; nt++) {
            int gc = n0 + wn * 32 + nt * 8 + t4 * 2;
            float b0 = bias[gc], b1 = bias[gc + 1];
            int gr0 = m0 + wm * 32 + mt * 16 + g;
            if (gr0 < M) {
                float2 o = make_float2(acc[mt][nt][0] + b0, acc[mt][nt][1] + b1);
                *(float2*)(Cm + (size_t)gr0 * N + gc) = o;
            }
            int gr1 = gr0 + 8;
            if (gr1 < M) {
                float2 o = make_float2(acc[mt][nt][2] + b0, acc[mt][nt][3] + b1);
                *(float2*)(Cm + (size_t)gr1 * N + gc) = o;
            }
        }
    }
}

// ---------------- layernorm (512 cols, optional residual) ----------------
__device__ __forceinline__ float block_reduce_sum(float v, float* sh) {
    int lane = threadIdx.x & 31, warp = threadIdx.x >> 5;
#pragma unroll
    for (int o = 16; o; o >>= 1) v += __shfl_xor_sync(0xffffffffu, v, o);
    if (lane == 0) sh[warp] = v;
    __syncthreads();
    if (warp == 0) {
        float t = (lane < 8) ? sh[lane] : 0.f;
#pragma unroll
        for (int o = 4; o; o >>= 1) t += __shfl_xor_sync(0xffffffffu, t, o);
        if (lane == 0) sh[0] = t;
    }
    __syncthreads();
    float r = sh[0];
    __syncthreads();
    return r;
}

__global__ void ln_kernel(const float* __restrict__ in, const float* __restrict__ resid,
                          const float* __restrict__ g, const float* __restrict__ bb,
                          float* __restrict__ out) {
    __shared__ float sh[32];
    int row = blockIdx.x, tid = threadIdx.x;  // 256 threads, 2 elems/thread
    size_t base = (size_t)row * 512;
    float x0 = in[base + tid], x1 = in[base + 256 + tid];
    if (resid) { x0 += resid[base + tid]; x1 += resid[base + 256 + tid]; }
    float mu = block_reduce_sum(x0 + x1, sh) * (1.f / 512.f);
    float d0 = x0 - mu, d1 = x1 - mu;
    float var = block_reduce_sum(d0 * d0 + d1 * d1, sh) * (1.f / 512.f);
    float rstd = rsqrtf(var + 1e-5f);
    out[base + tid]       = d0 * rstd * g[tid] + bb[tid];
    out[base + 256 + tid] = d1 * rstd * g[tid + 256] + bb[tid + 256];
}

// ---------------- attention: 16 queries x 225 keys x 64, one block per (b,h) ----------------
__global__ void attn_kernel() {
    __shared__ float qs[16 * 64];
    __shared__ float sc[16][228];
    int bh = blockIdx.x;
    int b = bh >> 3, h = bh & 7;
    int tid = threadIdx.x;  // 256
    for (int i = tid; i < 1024; i += 256)
        qs[i] = g_QKV[(size_t)(b * 16 + (i >> 6)) * 1536 + h * 64 + (i & 63)];
    __syncthreads();
    for (int idx = tid; idx < 16 * 225; idx += 256) {
        int p = idx / 225, l = idx - p * 225;
        const float* kr = g_QKV + (size_t)(kPatchRows + b * kL + l) * 1536 + 512 + h * 64;
        float s = 0.f;
#pragma unroll
        for (int d = 0; d < 64; d++) s += qs[p * 64 + d] * kr[d];
        sc[p][l] = s * 0.125f;  // 1/sqrt(64)
    }
    __syncthreads();
    int warp = tid >> 5, lane = tid & 31;
    for (int p = warp; p < 16; p += 8) {
        float mx = -1e30f;
        for (int l = lane; l < 225; l += 32) mx = fmaxf(mx, sc[p][l]);
#pragma unroll
        for (int o = 16; o; o >>= 1) mx = fmaxf(mx, __shfl_xor_sync(0xffffffffu, mx, o));
        float sum = 0.f;
        for (int l = lane; l < 225; l += 32) { float e = __expf(sc[p][l] - mx); sc[p][l] = e; sum += e; }
#pragma unroll
        for (int o = 16; o; o >>= 1) sum += __shfl_xor_sync(0xffffffffu, sum, o);
        float inv = 1.f / sum;
        for (int l = lane; l < 225; l += 32) sc[p][l] *= inv;
    }
    __syncthreads();
    for (int i = tid; i < 1024; i += 256) {
        int p = i >> 6, d = i & 63;
        const float* vbase = g_QKV + (size_t)(kPatchRows + b * kL) * 1536 + 1024 + h * 64 + d;
        float s = 0.f;
        for (int l = 0; l < 225; l++) s += sc[p][l] * vbase[(size_t)l * 1536];
        g_attn[(size_t)(b * 16 + p) * 512 + h * 64 + d] = s;
    }
}

// ---------------- MLP epilogue ----------------
__global__ void gelu_res_kernel() {
    int i = blockIdx.x * blockDim.x + threadIdx.x;
    if (i >= kPatchRows * kE) return;
    float hv = g_hid[i];
    g_xm[i] = 0.5f * hv * (1.f + erff(hv * 0.70710678118654752f)) + g_res[i];
}

__global__ void outs_kernel(const float* __restrict__ Wc, const float* __restrict__ bc) {
    int t = threadIdx.x;  // 256 = 128 rows x 2
    int row = t >> 1, j = t & 1;
    const float* x = g_xm + (size_t)row * 512;
    const float* w = Wc + j * 512;
    float s = 0.f;
    for (int k = 0; k < 512; k++) s += x[k] * w[k];
    g_outs[row * 2 + j] = s + bc[j];
}

// ---------------- segment mean + final scatter ----------------
__global__ void zero_seg_kernel() {
    int t = threadIdx.x;
    if (t < kB * 17 * 3) g_sums[t] = 0.f;
    if (t < kB * 17) g_cnt[t] = 0.f;
}

__global__ void seg_kernel(const float* __restrict__ probs, const int* __restrict__ masks) {
    __shared__ float ssum[51];
    __shared__ float scnt[17];
    int t = threadIdx.x;  // 256
    if (t < 51) ssum[t] = 0.f;
    if (t < 17) scnt[t] = 0.f;
    __syncthreads();
    int b = blockIdx.x >> 6;         // 64 blocks per image
    int chunk = blockIdx.x & 63;     // 1024 pixels per block
    int base = chunk * 1024;
#pragma unroll
    for (int k = 0; k < 4; k++) {
        int pix = base + k * 256 + t;
        int lab = masks[b * 65536 + pix];
        atomicAdd(&scnt[lab], 1.f);
#pragma unroll
        for (int c = 0; c < 3; c++)
            atomicAdd(&ssum[lab * 3 + c], probs[((size_t)(b * 3 + c)) * 65536 + pix]);
    }
    __syncthreads();
    if (t < 51) atomicAdd(&g_sums[b * 51 + t], ssum[t]);
    if (t < 17) atomicAdd(&g_cnt[b * 17 + t], scnt[t]);
}

__global__ void newv_kernel() {
    int t = threadIdx.x;  // 128
    if (t < 24) { int b = t / 3, c = t % 3; g_newv[b * 51 + c] = 0.f; }  // label 0 rows
    int b = t >> 4, p = t & 15, lab = p + 1;
    float denom = fmaxf(g_cnt[b * 17 + lab], 1.f);
    float m0 = g_sums[(b * 17 + lab) * 3 + 0] / denom + 1e-6f;
    float m1 = g_sums[(b * 17 + lab) * 3 + 1] / denom + 1e-6f;
    float m2 = g_sums[(b * 17 + lab) * 3 + 2] / denom + 1e-6f;
    float o0 = g_outs[(b * 16 + p) * 2 + 0], o1 = g_outs[(b * 16 + p) * 2 + 1];
    float n0 = m0 / (0.5f * (m1 + m2)) * (0.5f * (o0 + o1));
    g_newv[(b * 17 + lab) * 3 + 0] = n0;
    g_newv[(b * 17 + lab) * 3 + 1] = o0;
    g_newv[(b * 17 + lab) * 3 + 2] = o1;
}

__global__ void scatter_kernel(const float* __restrict__ probs, const int* __restrict__ masks,
                               float* __restrict__ out) {
    int i = blockIdx.x * blockDim.x + threadIdx.x;
    if (i >= kB * 65536) return;
    int b = i >> 16, pix = i & 65535;
    int lab = masks[i];
#pragma unroll
    for (int c = 0; c < 3; c++) {
        size_t o = ((size_t)(b * 3 + c)) * 65536 + pix;
        out[o] = (lab > 0) ? g_newv[(b * 17 + lab) * 3 + c] : probs[o];
    }
}

// ---------------- launch ----------------
extern "C" void kernel_launch(void* const* d_in, const int* /*in_sizes*/, int /*n_in*/,
                              void* d_out, int /*out_size*/) {
    const float* features = (const float*)d_in[0];
    const float* probs    = (const float*)d_in[1];
    const float* patches  = (const float*)d_in[2];
    const int*   masks    = (const int*)d_in[3];
    const float* ln_g = (const float*)d_in[4];
    const float* ln_b = (const float*)d_in[5];
    const float* Wr   = (const float*)d_in[6];
    const float* br   = (const float*)d_in[7];
    const float* Wqkv = (const float*)d_in[8];
    const float* bqkv = (const float*)d_in[9];
    const float* Wo   = (const float*)d_in[10];
    const float* bo   = (const float*)d_in[11];
    const float* Wm   = (const float*)d_in[12];
    const float* bm   = (const float*)d_in[13];
    const float* Wc   = (const float*)d_in[14];
    const float* bc   = (const float*)d_in[15];
    float* out = (float*)d_out;

    float *pX, *pY, *pYn, *pQKV, *pAttn, *pProj, *pRes, *pHid;
    cudaGetSymbolAddress((void**)&pX, g_X);
    cudaGetSymbolAddress((void**)&pY, g_Y);
    cudaGetSymbolAddress((void**)&pYn, g_Yn);
    cudaGetSymbolAddress((void**)&pQKV, g_QKV);
    cudaGetSymbolAddress((void**)&pAttn, g_attn);
    cudaGetSymbolAddress((void**)&pProj, g_proj);
    cudaGetSymbolAddress((void**)&pRes, g_res);
    cudaGetSymbolAddress((void**)&pHid, g_hid);

    pool_features_kernel<<<(kB * 16 * 128 * 128) / 256, 256>>>(features);
    pool_patches_kernel<<<(kPatchRows * kFV) / 256, 256>>>(patches);
    gather_blocks_kernel<<<(kB * kL * kFV) / 256, 256>>>();

    // patch2vec: (1928,4096)@(4096,512)^T
    gemm_tc_kernel<<<dim3(512 / 64, (kRows + 127) / 128), 256>>>(pX, Wr, br, pY, kRows, 512, 4096);
    ln_kernel<<<kRows, 256>>>(pY, nullptr, ln_g, ln_b, pYn);

    // fused QKV: (1928,512)@(512,1536)^T
    gemm_tc_kernel<<<dim3(1536 / 64, (kRows + 127) / 128), 256>>>(pYn, Wqkv, bqkv, pQKV, kRows, 1536, 512);
    attn_kernel<<<kB * kNH, 256>>>();

    // out proj + residual LN
    gemm_tc_kernel<<<dim3(512 / 64, 1), 256>>>(pAttn, Wo, bo, pProj, kPatchRows, 512, 512);
    ln_kernel<<<kPatchRows, 256>>>(pProj, pYn, ln_g, ln_b, pRes);

    // MLP
    gemm_tc_kernel<<<dim3(512 / 64, 1), 256>>>(pRes, Wm, bm, pHid, kPatchRows, 512, 512);
    gelu_res_kernel<<<(kPatchRows * kE) / 256, 256>>>();
    outs_kernel<<<1, 256>>>(Wc, bc);

    // segment statistics + final output
    zero_seg_kernel<<<1, 512>>>();
    seg_kernel<<<kB * 64, 256>>>(probs, masks);
    newv_kernel<<<1, 128>>>();
    scatter_kernel<<<(kB * 65536) / 256, 256>>>(probs, masks, out);
}

// round 5
// speedup vs baseline: 1.9207x; 1.3134x over previous
#include <cuda_runtime.h>
#include <cuda_bf16.h>
#include <math.h>
#include <stdint.h>

// ---------------- problem constants ----------------
constexpr int kB = 8, kC = 64, kH = 256, kW = 256;
constexpr int kE = 512, kNH = 8, kHD = 64;
constexpr int kP = 16, kN = 15, kL = 225;      // n=15 windows, L=225 blocks/img
constexpr int kFV = 4096;                       // 16 ch-groups * 16 * 16
constexpr int kRows = kB * (kP + kL);           // 1928 rows
constexpr int kPatchRows = kB * kP;             // 128

// ---------------- device scratch ----------------
__device__ float g_pooledF[kB * 16 * 128 * 128];
// pre-split bf16 planes, packed as u32 of 2 adjacent-K bf16
__device__ uint32_t g_Xp0[kRows * (kFV / 2)];
__device__ uint32_t g_Xp1[kRows * (kFV / 2)];
__device__ uint32_t g_Wrp0[kE * (kFV / 2)], g_Wrp1[kE * (kFV / 2)];
__device__ uint32_t g_Wqkvp0[3 * kE * (kE / 2)], g_Wqkvp1[3 * kE * (kE / 2)];
__device__ uint32_t g_Wop0[kE * (kE / 2)], g_Wop1[kE * (kE / 2)];
__device__ uint32_t g_Wmp0[kE * (kE / 2)], g_Wmp1[kE * (kE / 2)];
__device__ uint32_t g_Ynp0[kRows * (kE / 2)], g_Ynp1[kRows * (kE / 2)];
__device__ uint32_t g_attnp0[kPatchRows * (kE / 2)], g_attnp1[kPatchRows * (kE / 2)];
__device__ uint32_t g_resp0[kPatchRows * (kE / 2)], g_resp1[kPatchRows * (kE / 2)];

__device__ float g_Y[kRows * kE];
__device__ float g_Yn[kRows * kE];
__device__ float g_QKV[kRows * 3 * kE];
__device__ float g_proj[kPatchRows * kE];
__device__ float g_res[kPatchRows * kE];
__device__ float g_hid[kPatchRows * kE];
__device__ float g_xm[kPatchRows * kE];
__device__ float g_outs[kPatchRows * 2];
__device__ float g_sums[kB * 17 * 3];
__device__ float g_cnt[kB * 17];
__device__ float g_newv[kB * 17 * 3];

// ---------------- bf16 split/pack ----------------
__device__ __forceinline__ void pack_pair(float x0, float x1, uint32_t& w0, uint32_t& w1) {
    __nv_bfloat162 h = __floats2bfloat162_rn(x0, x1);
    float r0 = x0 - __low2float(h);
    float r1 = x1 - __high2float(h);
    __nv_bfloat162 l = __floats2bfloat162_rn(r0, r1);
    w0 = *reinterpret_cast<uint32_t*>(&h);
    w1 = *reinterpret_cast<uint32_t*>(&l);
}

// ---------------- pooling ----------------
__global__ void pool_features_kernel(const float* __restrict__ f) {
    int i = blockIdx.x * blockDim.x + threadIdx.x;
    if (i >= kB * 16 * 128 * 128) return;
    int x = i & 127, y = (i >> 7) & 127, cg = (i >> 14) & 15, b = i >> 18;
    float s = 0.f;
#pragma unroll
    for (int cc = 0; cc < 4; cc++) {
        const float* base = f + ((size_t)(b * kC + cg * 4 + cc) * kH + 2 * y) * kW + 2 * x;
#pragma unroll
        for (int dy = 0; dy < 2; dy++) {
            float2 v = *(const float2*)(base + dy * kW);
            s += v.x + v.y;
        }
    }
    g_pooledF[i] = s * (1.f / 16.f);
}

// patches -> Xp rows [0,128), pair of adjacent ww per thread
__global__ void pool_patches_kernel(const float* __restrict__ p) {
    int i = blockIdx.x * blockDim.x + threadIdx.x;
    if (i >= kPatchRows * (kFV / 2)) return;
    int v2 = i & 2047, n = i >> 11;
    int w2 = v2 & 7, hh = (v2 >> 3) & 15, cg = v2 >> 7;
    float s0 = 0.f, s1 = 0.f;
#pragma unroll
    for (int cc = 0; cc < 4; cc++) {
        const float* base = p + (size_t)n * 65536 + (cg * 4 + cc) * 1024 + 4 * w2;
#pragma unroll
        for (int dh = 0; dh < 2; dh++) {
            float4 q = *(const float4*)(base + (2 * hh + dh) * 32);
            s0 += q.x + q.y;
            s1 += q.z + q.w;
        }
    }
    uint32_t w0, w1;
    pack_pair(s0 * (1.f / 16.f), s1 * (1.f / 16.f), w0, w1);
    g_Xp0[(size_t)n * 2048 + v2] = w0;
    g_Xp1[(size_t)n * 2048 + v2] = w1;
}

__global__ void gather_blocks_kernel() {
    int i = blockIdx.x * blockDim.x + threadIdx.x;
    if (i >= kB * kL * (kFV / 2)) return;
    int v2 = i & 2047, r = i >> 11;
    int b = r / kL, l = r - b * kL;
    int li = l / kN, lj = l - li * kN;
    int w2 = v2 & 7, hh = (v2 >> 3) & 15, cg = v2 >> 7;
    float2 q = *(const float2*)&g_pooledF[((size_t)(b * 16 + cg) * 128 + (8 * li + hh)) * 128 + 8 * lj + 2 * w2];
    uint32_t w0, w1;
    pack_pair(q.x, q.y, w0, w1);
    g_Xp0[(size_t)(kPatchRows + r) * 2048 + v2] = w0;
    g_Xp1[(size_t)(kPatchRows + r) * 2048 + v2] = w1;
}

// weights: flat pair split
__global__ void split_weight_kernel(const float* __restrict__ W, uint32_t* __restrict__ P0,
                                    uint32_t* __restrict__ P1, int total2) {
    int i = blockIdx.x * blockDim.x + threadIdx.x;
    if (i >= total2) return;
    float2 x = *(const float2*)&W[2 * i];
    uint32_t w0, w1;
    pack_pair(x.x, x.y, w0, w1);
    P0[i] = w0;
    P1[i] = w1;
}

// ---------------- bf16x2 (3-mma) tensor GEMM: C[M,N] = A@Bw^T + bias ----------------
__device__ __forceinline__ void mma_bf16(float* d, const uint32_t* a, const uint32_t* b) {
    asm volatile(
        "mma.sync.aligned.m16n8k16.row.col.f32.bf16.bf16.f32 "
        "{%0,%1,%2,%3}, {%4,%5,%6,%7}, {%8,%9}, {%0,%1,%2,%3};"
        : "+f"(d[0]), "+f"(d[1]), "+f"(d[2]), "+f"(d[3])
        : "r"(a[0]), "r"(a[1]), "r"(a[2]), "r"(a[3]), "r"(b[0]), "r"(b[1]));
}

__device__ __forceinline__ void cp_async16(void* smem, const void* g, bool valid) {
    uint32_t s = (uint32_t)__cvta_generic_to_shared(smem);
    int sz = valid ? 16 : 0;
    asm volatile("cp.async.cg.shared.global [%0], [%1], 16, %2;\n" :: "r"(s), "l"(g), "r"(sz));
}
__device__ __forceinline__ void cp_async_commit() { asm volatile("cp.async.commit_group;\n" ::); }
template <int NN>
__device__ __forceinline__ void cp_async_wait() { asm volatile("cp.async.wait_group %0;\n" :: "n"(NN)); }

// GPAD must keep each smem row 16B-aligned for cp.async: 20 u32 = 80 B = 5*16B. OK.
// Fragment LDS bank check: bank = (20*g + t4) mod 32, g in 0..7 -> {0,20,8,28,16,4,24,12} distinct.
constexpr int GPAD = 20;
constexpr int GEMM_SMEM_BYTES = (2 * 128 * GPAD * 2 + 2 * 64 * GPAD * 2) * 4;  // 61,440

__global__ __launch_bounds__(256) void gemm_bf16_kernel(
    const uint32_t* __restrict__ A0, const uint32_t* __restrict__ A1,
    const uint32_t* __restrict__ B0, const uint32_t* __restrict__ B1,
    const float* __restrict__ bias, float* __restrict__ Cm,
    int M, int N, int K2)   // K2 = K/2 (u32 words per row)
{
    extern __shared__ uint32_t sm[];
    uint32_t* As0 = sm;                       // [2][128][GPAD]
    uint32_t* As1 = As0 + 2 * 128 * GPAD;
    uint32_t* Bs0 = As1 + 2 * 128 * GPAD;     // [2][64][GPAD]
    uint32_t* Bs1 = Bs0 + 2 * 64 * GPAD;

    const int tid = threadIdx.x;
    const int lane = tid & 31, wid = tid >> 5;
    const int wm = wid >> 1, wn = wid & 1;    // 4x2 warps, each 32x32
    const int g = lane >> 2, t4 = lane & 3;
    const int m0 = blockIdx.y * 128, n0 = blockIdx.x * 64;

    float acc[2][4][4];
#pragma unroll
    for (int mt = 0; mt < 2; mt++)
#pragma unroll
        for (int nt = 0; nt < 4; nt++)
#pragma unroll
            for (int i = 0; i < 4; i++) acc[mt][nt][i] = 0.f;

    auto load_stage = [&](int buf, int kt) {
        int k0 = kt * 16;
#pragma unroll
        for (int i = 0; i < 2; i++) {
            int idx = tid + i * 256;
            int row = idx >> 2, c4 = (idx & 3) * 4;
            bool v = (m0 + row) < M;
            size_t off = (size_t)(v ? (m0 + row) : 0) * K2 + k0 + c4;
            cp_async16(&As0[(buf * 128 + row) * GPAD + c4], A0 + off, v);
            cp_async16(&As1[(buf * 128 + row) * GPAD + c4], A1 + off, v);
        }
        {
            int row = tid >> 2, c4 = (tid & 3) * 4;
            size_t off = (size_t)(n0 + row) * K2 + k0 + c4;
            cp_async16(&Bs0[(buf * 64 + row) * GPAD + c4], B0 + off, true);
            cp_async16(&Bs1[(buf * 64 + row) * GPAD + c4], B1 + off, true);
        }
        cp_async_commit();
    };

    auto compute = [&](int buf) {
#pragma unroll
        for (int sl = 0; sl < 2; sl++) {
            int ks = sl * 8;
            uint32_t a0[2][4], a1[2][4], b0[4][2], b1[4][2];
#pragma unroll
            for (int mt = 0; mt < 2; mt++) {
                int mr = buf * 128 + wm * 32 + mt * 16;
                a0[mt][0] = As0[(mr + g) * GPAD + ks + t4];
                a0[mt][1] = As0[(mr + g + 8) * GPAD + ks + t4];
                a0[mt][2] = As0[(mr + g) * GPAD + ks + t4 + 4];
                a0[mt][3] = As0[(mr + g + 8) * GPAD + ks + t4 + 4];
                a1[mt][0] = As1[(mr + g) * GPAD + ks + t4];
                a1[mt][1] = As1[(mr + g + 8) * GPAD + ks + t4];
                a1[mt][2] = As1[(mr + g) * GPAD + ks + t4 + 4];
                a1[mt][3] = As1[(mr + g + 8) * GPAD + ks + t4 + 4];
            }
#pragma unroll
            for (int nt = 0; nt < 4; nt++) {
                int nr = buf * 64 + wn * 32 + nt * 8 + g;
                b0[nt][0] = Bs0[nr * GPAD + ks + t4];
                b0[nt][1] = Bs0[nr * GPAD + ks + t4 + 4];
                b1[nt][0] = Bs1[nr * GPAD + ks + t4];
                b1[nt][1] = Bs1[nr * GPAD + ks + t4 + 4];
            }
#pragma unroll
            for (int mt = 0; mt < 2; mt++)
#pragma unroll
                for (int nt = 0; nt < 4; nt++) {
                    mma_bf16(acc[mt][nt], a0[mt], b0[nt]);  // hi*hi
                    mma_bf16(acc[mt][nt], a0[mt], b1[nt]);  // hi*lo
                    mma_bf16(acc[mt][nt], a1[mt], b0[nt]);  // lo*hi
                }
        }
    };

    const int kTiles = K2 / 16;
    load_stage(0, 0);
    int buf = 0;
    for (int kt = 0; kt < kTiles; kt++) {
        if (kt + 1 < kTiles) {
            load_stage(buf ^ 1, kt + 1);
            cp_async_wait<1>();
        } else {
            cp_async_wait<0>();
        }
        __syncthreads();
        compute(buf);
        __syncthreads();
        buf ^= 1;
    }

#pragma unroll
    for (int mt = 0; mt < 2; mt++) {
#pragma unroll
        for (int nt = 0; nt < 4; nt++) {
            int gc = n0 + wn * 32 + nt * 8 + t4 * 2;
            float b0v = bias[gc], b1v = bias[gc + 1];
            int gr0 = m0 + wm * 32 + mt * 16 + g;
            if (gr0 < M) {
                float2 o = make_float2(acc[mt][nt][0] + b0v, acc[mt][nt][1] + b1v);
                *(float2*)(Cm + (size_t)gr0 * N + gc) = o;
            }
            int gr1 = gr0 + 8;
            if (gr1 < M) {
                float2 o = make_float2(acc[mt][nt][2] + b0v, acc[mt][nt][3] + b1v);
                *(float2*)(Cm + (size_t)gr1 * N + gc) = o;
            }
        }
    }
}

// ---------------- layernorm: plain + packed bf16 outputs ----------------
__device__ __forceinline__ float block_reduce_sum(float v, float* sh) {
    int lane = threadIdx.x & 31, warp = threadIdx.x >> 5;
#pragma unroll
    for (int o = 16; o; o >>= 1) v += __shfl_xor_sync(0xffffffffu, v, o);
    if (lane == 0) sh[warp] = v;
    __syncthreads();
    if (warp == 0) {
        float t = (lane < 8) ? sh[lane] : 0.f;
#pragma unroll
        for (int o = 4; o; o >>= 1) t += __shfl_xor_sync(0xffffffffu, t, o);
        if (lane == 0) sh[0] = t;
    }
    __syncthreads();
    float r = sh[0];
    __syncthreads();
    return r;
}

__global__ void ln_kernel(const float* __restrict__ in, const float* __restrict__ resid,
                          const float* __restrict__ g, const float* __restrict__ bb,
                          float* __restrict__ out, uint32_t* __restrict__ p0,
                          uint32_t* __restrict__ p1) {
    __shared__ float sh[32];
    int row = blockIdx.x, tid = threadIdx.x;  // 256 threads, 2 adjacent cols each
    size_t base = (size_t)row * 512;
    float2 x = *(const float2*)&in[base + 2 * tid];
    if (resid) {
        float2 r = *(const float2*)&resid[base + 2 * tid];
        x.x += r.x; x.y += r.y;
    }
    float mu = block_reduce_sum(x.x + x.y, sh) * (1.f / 512.f);
    float d0 = x.x - mu, d1 = x.y - mu;
    float var = block_reduce_sum(d0 * d0 + d1 * d1, sh) * (1.f / 512.f);
    float rstd = rsqrtf(var + 1e-5f);
    float2 gv = *(const float2*)&g[2 * tid];
    float2 bv = *(const float2*)&bb[2 * tid];
    float y0 = d0 * rstd * gv.x + bv.x;
    float y1 = d1 * rstd * gv.y + bv.y;
    *(float2*)&out[base + 2 * tid] = make_float2(y0, y1);
    uint32_t w0, w1;
    pack_pair(y0, y1, w0, w1);
    p0[(size_t)row * 256 + tid] = w0;
    p1[(size_t)row * 256 + tid] = w1;
}

// ---------------- attention ----------------
__global__ void attn_kernel() {
    __shared__ float qs[16 * 64];
    __shared__ float sc[16][228];
    int bh = blockIdx.x;
    int b = bh >> 3, h = bh & 7;
    int tid = threadIdx.x;  // 256
    for (int i = tid; i < 1024; i += 256)
        qs[i] = g_QKV[(size_t)(b * 16 + (i >> 6)) * 1536 + h * 64 + (i & 63)];
    __syncthreads();
    for (int idx = tid; idx < 16 * 225; idx += 256) {
        int p = idx / 225, l = idx - p * 225;
        const float* kr = g_QKV + (size_t)(kPatchRows + b * kL + l) * 1536 + 512 + h * 64;
        float s = 0.f;
#pragma unroll
        for (int d = 0; d < 64; d++) s += qs[p * 64 + d] * kr[d];
        sc[p][l] = s * 0.125f;
    }
    __syncthreads();
    int warp = tid >> 5, lane = tid & 31;
    for (int p = warp; p < 16; p += 8) {
        float mx = -1e30f;
        for (int l = lane; l < 225; l += 32) mx = fmaxf(mx, sc[p][l]);
#pragma unroll
        for (int o = 16; o; o >>= 1) mx = fmaxf(mx, __shfl_xor_sync(0xffffffffu, mx, o));
        float sum = 0.f;
        for (int l = lane; l < 225; l += 32) { float e = __expf(sc[p][l] - mx); sc[p][l] = e; sum += e; }
#pragma unroll
        for (int o = 16; o; o >>= 1) sum += __shfl_xor_sync(0xffffffffu, sum, o);
        float inv = 1.f / sum;
        for (int l = lane; l < 225; l += 32) sc[p][l] *= inv;
    }
    __syncthreads();
    // output as packed bf16 pairs (adjacent d)
    for (int i = tid; i < 512; i += 256) {
        int p = i >> 5, d2 = i & 31;
        const float* vbase = g_QKV + (size_t)(kPatchRows + b * kL) * 1536 + 1024 + h * 64 + 2 * d2;
        float s0 = 0.f, s1 = 0.f;
        for (int l = 0; l < 225; l++) {
            float2 v = *(const float2*)(vbase + (size_t)l * 1536);
            float w = sc[p][l];
            s0 += w * v.x;
            s1 += w * v.y;
        }
        uint32_t w0, w1;
        pack_pair(s0, s1, w0, w1);
        size_t oi = (size_t)(b * 16 + p) * 256 + h * 32 + d2;
        g_attnp0[oi] = w0;
        g_attnp1[oi] = w1;
    }
}

// ---------------- MLP epilogue ----------------
__global__ void gelu_res_kernel() {
    int i = blockIdx.x * blockDim.x + threadIdx.x;
    if (i >= kPatchRows * kE) return;
    float hv = g_hid[i];
    g_xm[i] = 0.5f * hv * (1.f + erff(hv * 0.70710678118654752f)) + g_res[i];
}

__global__ void outs_kernel(const float* __restrict__ Wc, const float* __restrict__ bc) {
    int t = threadIdx.x;  // 256 = 128 rows x 2
    int row = t >> 1, j = t & 1;
    const float* x = g_xm + (size_t)row * 512;
    const float* w = Wc + j * 512;
    float s = 0.f;
    for (int k = 0; k < 512; k++) s += x[k] * w[k];
    g_outs[row * 2 + j] = s + bc[j];
}

// ---------------- segment mean + final scatter ----------------
__global__ void zero_seg_kernel() {
    int t = threadIdx.x;
    if (t < kB * 17 * 3) g_sums[t] = 0.f;
    if (t < kB * 17) g_cnt[t] = 0.f;
}

__global__ void seg_kernel(const float* __restrict__ probs, const int* __restrict__ masks) {
    __shared__ float ssum[51];
    __shared__ float scnt[17];
    int t = threadIdx.x;  // 256
    if (t < 51) ssum[t] = 0.f;
    if (t < 17) scnt[t] = 0.f;
    __syncthreads();
    int b = blockIdx.x >> 6;
    int chunk = blockIdx.x & 63;
    int base = chunk * 1024;
#pragma unroll
    for (int k = 0; k < 4; k++) {
        int pix = base + k * 256 + t;
        int lab = masks[b * 65536 + pix];
        atomicAdd(&scnt[lab], 1.f);
#pragma unroll
        for (int c = 0; c < 3; c++)
            atomicAdd(&ssum[lab * 3 + c], probs[((size_t)(b * 3 + c)) * 65536 + pix]);
    }
    __syncthreads();
    if (t < 51) atomicAdd(&g_sums[b * 51 + t], ssum[t]);
    if (t < 17) atomicAdd(&g_cnt[b * 17 + t], scnt[t]);
}

__global__ void newv_kernel() {
    int t = threadIdx.x;  // 128
    if (t < 24) { int b = t / 3, c = t % 3; g_newv[b * 51 + c] = 0.f; }
    int b = t >> 4, p = t & 15, lab = p + 1;
    float denom = fmaxf(g_cnt[b * 17 + lab], 1.f);
    float m0 = g_sums[(b * 17 + lab) * 3 + 0] / denom + 1e-6f;
    float m1 = g_sums[(b * 17 + lab) * 3 + 1] / denom + 1e-6f;
    float m2 = g_sums[(b * 17 + lab) * 3 + 2] / denom + 1e-6f;
    float o0 = g_outs[(b * 16 + p) * 2 + 0], o1 = g_outs[(b * 16 + p) * 2 + 1];
    float n0 = m0 / (0.5f * (m1 + m2)) * (0.5f * (o0 + o1));
    g_newv[(b * 17 + lab) * 3 + 0] = n0;
    g_newv[(b * 17 + lab) * 3 + 1] = o0;
    g_newv[(b * 17 + lab) * 3 + 2] = o1;
}

__global__ void scatter_kernel(const float* __restrict__ probs, const int* __restrict__ masks,
                               float* __restrict__ out) {
    int i = blockIdx.x * blockDim.x + threadIdx.x;
    if (i >= kB * 65536) return;
    int b = i >> 16, pix = i & 65535;
    int lab = masks[i];
#pragma unroll
    for (int c = 0; c < 3; c++) {
        size_t o = ((size_t)(b * 3 + c)) * 65536 + pix;
        out[o] = (lab > 0) ? g_newv[(b * 17 + lab) * 3 + c] : probs[o];
    }
}

// ---------------- launch ----------------
extern "C" void kernel_launch(void* const* d_in, const int* /*in_sizes*/, int /*n_in*/,
                              void* d_out, int /*out_size*/) {
    const float* features = (const float*)d_in[0];
    const float* probs    = (const float*)d_in[1];
    const float* patches  = (const float*)d_in[2];
    const int*   masks    = (const int*)d_in[3];
    const float* ln_g = (const float*)d_in[4];
    const float* ln_b = (const float*)d_in[5];
    const float* Wr   = (const float*)d_in[6];
    const float* br   = (const float*)d_in[7];
    const float* Wqkv = (const float*)d_in[8];
    const float* bqkv = (const float*)d_in[9];
    const float* Wo   = (const float*)d_in[10];
    const float* bo   = (const float*)d_in[11];
    const float* Wm   = (const float*)d_in[12];
    const float* bm   = (const float*)d_in[13];
    const float* Wc   = (const float*)d_in[14];
    const float* bc   = (const float*)d_in[15];
    float* out = (float*)d_out;

    cudaFuncSetAttribute(gemm_bf16_kernel, cudaFuncAttributeMaxDynamicSharedMemorySize,
                         GEMM_SMEM_BYTES);

    uint32_t *pXp0, *pXp1, *pWrp0, *pWrp1, *pWqkvp0, *pWqkvp1, *pWop0, *pWop1, *pWmp0, *pWmp1;
    uint32_t *pYnp0, *pYnp1, *pAttnp0, *pAttnp1, *pResp0, *pResp1;
    float *pY, *pYn, *pQKV, *pProj, *pRes, *pHid;
    cudaGetSymbolAddress((void**)&pXp0, g_Xp0);
    cudaGetSymbolAddress((void**)&pXp1, g_Xp1);
    cudaGetSymbolAddress((void**)&pWrp0, g_Wrp0);
    cudaGetSymbolAddress((void**)&pWrp1, g_Wrp1);
    cudaGetSymbolAddress((void**)&pWqkvp0, g_Wqkvp0);
    cudaGetSymbolAddress((void**)&pWqkvp1, g_Wqkvp1);
    cudaGetSymbolAddress((void**)&pWop0, g_Wop0);
    cudaGetSymbolAddress((void**)&pWop1, g_Wop1);
    cudaGetSymbolAddress((void**)&pWmp0, g_Wmp0);
    cudaGetSymbolAddress((void**)&pWmp1, g_Wmp1);
    cudaGetSymbolAddress((void**)&pYnp0, g_Ynp0);
    cudaGetSymbolAddress((void**)&pYnp1, g_Ynp1);
    cudaGetSymbolAddress((void**)&pAttnp0, g_attnp0);
    cudaGetSymbolAddress((void**)&pAttnp1, g_attnp1);
    cudaGetSymbolAddress((void**)&pResp0, g_resp0);
    cudaGetSymbolAddress((void**)&pResp1, g_resp1);
    cudaGetSymbolAddress((void**)&pY, g_Y);
    cudaGetSymbolAddress((void**)&pYn, g_Yn);
    cudaGetSymbolAddress((void**)&pQKV, g_QKV);
    cudaGetSymbolAddress((void**)&pProj, g_proj);
    cudaGetSymbolAddress((void**)&pRes, g_res);
    cudaGetSymbolAddress((void**)&pHid, g_hid);

    // producers (pre-split everything)
    pool_features_kernel<<<(kB * 16 * 128 * 128) / 256, 256>>>(features);
    pool_patches_kernel<<<(kPatchRows * (kFV / 2)) / 256, 256>>>(patches);
    gather_blocks_kernel<<<(kB * kL * (kFV / 2)) / 256, 256>>>();
    split_weight_kernel<<<(kE * kFV / 2) / 256, 256>>>(Wr, pWrp0, pWrp1, kE * kFV / 2);
    split_weight_kernel<<<(3 * kE * kE / 2) / 256, 256>>>(Wqkv, pWqkvp0, pWqkvp1, 3 * kE * kE / 2);
    split_weight_kernel<<<(kE * kE / 2) / 256, 256>>>(Wo, pWop0, pWop1, kE * kE / 2);
    split_weight_kernel<<<(kE * kE / 2) / 256, 256>>>(Wm, pWmp0, pWmp1, kE * kE / 2);

    // patch2vec: (1928,4096)@(4096,512)^T
    gemm_bf16_kernel<<<dim3(512 / 64, (kRows + 127) / 128), 256, GEMM_SMEM_BYTES>>>(
        pXp0, pXp1, pWrp0, pWrp1, br, pY, kRows, 512, kFV / 2);
    ln_kernel<<<kRows, 256>>>(pY, nullptr, ln_g, ln_b, pYn, pYnp0, pYnp1);

    // fused QKV: (1928,512)@(512,1536)^T
    gemm_bf16_kernel<<<dim3(1536 / 64, (kRows + 127) / 128), 256, GEMM_SMEM_BYTES>>>(
        pYnp0, pYnp1, pWqkvp0, pWqkvp1, bqkv, pQKV, kRows, 1536, kE / 2);
    attn_kernel<<<kB * kNH, 256>>>();

    // out proj + residual LN
    gemm_bf16_kernel<<<dim3(512 / 64, 1), 256, GEMM_SMEM_BYTES>>>(
        pAttnp0, pAttnp1, pWop0, pWop1, bo, pProj, kPatchRows, 512, kE / 2);
    ln_kernel<<<kPatchRows, 256>>>(pProj, pYn, ln_g, ln_b, pRes, pResp0, pResp1);

    // MLP
    gemm_bf16_kernel<<<dim3(512 / 64, 1), 256, GEMM_SMEM_BYTES>>>(
        pResp0, pResp1, pWmp0, pWmp1, bm, pHid, kPatchRows, 512, kE / 2);
    gelu_res_kernel<<<(kPatchRows * kE) / 256, 256>>>();
    outs_kernel<<<1, 256>>>(Wc, bc);

    // segment statistics + final output
    zero_seg_kernel<<<1, 512>>>();
    seg_kernel<<<kB * 64, 256>>>(probs, masks);
    newv_kernel<<<1, 128>>>();
    scatter_kernel<<<(kB * 65536) / 256, 256>>>(probs, masks, out);
}

// round 6
// speedup vs baseline: 2.5622x; 1.3340x over previous
#include <cuda_runtime.h>
#include <cuda_bf16.h>
#include <math.h>
#include <stdint.h>

// ---------------- problem constants ----------------
constexpr int kB = 8, kC = 64, kH = 256, kW = 256;
constexpr int kE = 512, kNH = 8, kHD = 64;
constexpr int kP = 16, kN = 15, kL = 225;      // n=15 windows, L=225 blocks/img
constexpr int kFV = 4096;                       // 16 ch-groups * 16 * 16
constexpr int kRows = kB * (kP + kL);           // 1928 rows
constexpr int kPatchRows = kB * kP;             // 128

// ---------------- device scratch ----------------
__device__ float g_pooledF[kB * 16 * 128 * 128];
// pre-split bf16 planes, packed as u32 of 2 adjacent-K bf16
__device__ uint32_t g_Xp0[kRows * (kFV / 2)];
__device__ uint32_t g_Xp1[kRows * (kFV / 2)];
__device__ uint32_t g_Wrp0[kE * (kFV / 2)], g_Wrp1[kE * (kFV / 2)];
__device__ uint32_t g_Wqkvp0[3 * kE * (kE / 2)], g_Wqkvp1[3 * kE * (kE / 2)];
__device__ uint32_t g_Wop0[kE * (kE / 2)], g_Wop1[kE * (kE / 2)];
__device__ uint32_t g_Wmp0[kE * (kE / 2)], g_Wmp1[kE * (kE / 2)];
__device__ uint32_t g_Ynp0[kRows * (kE / 2)], g_Ynp1[kRows * (kE / 2)];
__device__ uint32_t g_attnp0[kPatchRows * (kE / 2)], g_attnp1[kPatchRows * (kE / 2)];
__device__ uint32_t g_resp0[kPatchRows * (kE / 2)], g_resp1[kPatchRows * (kE / 2)];

__device__ float g_Y[kRows * kE];
__device__ float g_Y2[kRows * kE];   // split-K partial
__device__ float g_Yn[kRows * kE];
__device__ float g_QKV[kRows * 3 * kE];
__device__ float g_proj[kPatchRows * kE];
__device__ float g_res[kPatchRows * kE];
__device__ float g_hid[kPatchRows * kE];
__device__ float g_xm[kPatchRows * kE];
__device__ float g_outs[kPatchRows * 2];
__device__ float g_sums[kB * 17 * 3];
__device__ float g_cnt[kB * 17];
__device__ float g_newv[kB * 17 * 3];

// ---------------- bf16 split/pack ----------------
__device__ __forceinline__ void pack_pair(float x0, float x1, uint32_t& w0, uint32_t& w1) {
    __nv_bfloat162 h = __floats2bfloat162_rn(x0, x1);
    float r0 = x0 - __low2float(h);
    float r1 = x1 - __high2float(h);
    __nv_bfloat162 l = __floats2bfloat162_rn(r0, r1);
    w0 = *reinterpret_cast<uint32_t*>(&h);
    w1 = *reinterpret_cast<uint32_t*>(&l);
}

// ---------------- pooling ----------------
__global__ void pool_features_kernel(const float* __restrict__ f) {
    int i = blockIdx.x * blockDim.x + threadIdx.x;
    if (i >= kB * 16 * 128 * 128) return;
    int x = i & 127, y = (i >> 7) & 127, cg = (i >> 14) & 15, b = i >> 18;
    float s = 0.f;
#pragma unroll
    for (int cc = 0; cc < 4; cc++) {
        const float* base = f + ((size_t)(b * kC + cg * 4 + cc) * kH + 2 * y) * kW + 2 * x;
#pragma unroll
        for (int dy = 0; dy < 2; dy++) {
            float2 v = *(const float2*)(base + dy * kW);
            s += v.x + v.y;
        }
    }
    g_pooledF[i] = s * (1.f / 16.f);
}

// patches -> Xp rows [0,128)
__global__ void pool_patches_kernel(const float* __restrict__ p) {
    int i = blockIdx.x * blockDim.x + threadIdx.x;
    if (i >= kPatchRows * (kFV / 2)) return;
    int v2 = i & 2047, n = i >> 11;
    int w2 = v2 & 7, hh = (v2 >> 3) & 15, cg = v2 >> 7;
    float s0 = 0.f, s1 = 0.f;
#pragma unroll
    for (int cc = 0; cc < 4; cc++) {
        const float* base = p + (size_t)n * 65536 + (cg * 4 + cc) * 1024 + 4 * w2;
#pragma unroll
        for (int dh = 0; dh < 2; dh++) {
            float4 q = *(const float4*)(base + (2 * hh + dh) * 32);
            s0 += q.x + q.y;
            s1 += q.z + q.w;
        }
    }
    uint32_t w0, w1;
    pack_pair(s0 * (1.f / 16.f), s1 * (1.f / 16.f), w0, w1);
    g_Xp0[(size_t)n * 2048 + v2] = w0;
    g_Xp1[(size_t)n * 2048 + v2] = w1;
}

__global__ void gather_blocks_kernel() {
    int i = blockIdx.x * blockDim.x + threadIdx.x;
    if (i >= kB * kL * (kFV / 2)) return;
    int v2 = i & 2047, r = i >> 11;
    int b = r / kL, l = r - b * kL;
    int li = l / kN, lj = l - li * kN;
    int w2 = v2 & 7, hh = (v2 >> 3) & 15, cg = v2 >> 7;
    float2 q = *(const float2*)&g_pooledF[((size_t)(b * 16 + cg) * 128 + (8 * li + hh)) * 128 + 8 * lj + 2 * w2];
    uint32_t w0, w1;
    pack_pair(q.x, q.y, w0, w1);
    g_Xp0[(size_t)(kPatchRows + r) * 2048 + v2] = w0;
    g_Xp1[(size_t)(kPatchRows + r) * 2048 + v2] = w1;
}

// weights: flat pair split
__global__ void split_weight_kernel(const float* __restrict__ W, uint32_t* __restrict__ P0,
                                    uint32_t* __restrict__ P1, int total2) {
    int i = blockIdx.x * blockDim.x + threadIdx.x;
    if (i >= total2) return;
    float2 x = *(const float2*)&W[2 * i];
    uint32_t w0, w1;
    pack_pair(x.x, x.y, w0, w1);
    P0[i] = w0;
    P1[i] = w1;
}

// ---------------- bf16x2 (3-mma) tensor GEMM ----------------
__device__ __forceinline__ void mma_bf16(float* d, const uint32_t* a, const uint32_t* b) {
    asm volatile(
        "mma.sync.aligned.m16n8k16.row.col.f32.bf16.bf16.f32 "
        "{%0,%1,%2,%3}, {%4,%5,%6,%7}, {%8,%9}, {%0,%1,%2,%3};"
        : "+f"(d[0]), "+f"(d[1]), "+f"(d[2]), "+f"(d[3])
        : "r"(a[0]), "r"(a[1]), "r"(a[2]), "r"(a[3]), "r"(b[0]), "r"(b[1]));
}

__device__ __forceinline__ void cp_async16(void* smem, const void* g, bool valid) {
    uint32_t s = (uint32_t)__cvta_generic_to_shared(smem);
    int sz = valid ? 16 : 0;
    asm volatile("cp.async.cg.shared.global [%0], [%1], 16, %2;\n" :: "r"(s), "l"(g), "r"(sz));
}
__device__ __forceinline__ void cp_async_commit() { asm volatile("cp.async.commit_group;\n" ::); }
template <int NN>
__device__ __forceinline__ void cp_async_wait() { asm volatile("cp.async.wait_group %0;\n" :: "n"(NN)); }

// 20 u32 = 80 B row stride: 16B-aligned for cp.async, conflict-free fragment LDS.
constexpr int GPAD = 20;
constexpr int GEMM_SMEM_BYTES = (2 * 128 * GPAD * 2 + 2 * 64 * GPAD * 2) * 4;  // 61,440

// C[M,N] (+= optional bias) over K2len words starting at given pointers; row stride K2s.
__global__ __launch_bounds__(256) void gemm_bf16_kernel(
    const uint32_t* __restrict__ A0, const uint32_t* __restrict__ A1,
    const uint32_t* __restrict__ B0, const uint32_t* __restrict__ B1,
    const float* __restrict__ bias, float* __restrict__ Cm,
    int M, int N, int K2len, int K2s)
{
    extern __shared__ uint32_t sm[];
    uint32_t* As0 = sm;                       // [2][128][GPAD]
    uint32_t* As1 = As0 + 2 * 128 * GPAD;
    uint32_t* Bs0 = As1 + 2 * 128 * GPAD;     // [2][64][GPAD]
    uint32_t* Bs1 = Bs0 + 2 * 64 * GPAD;

    const int tid = threadIdx.x;
    const int lane = tid & 31, wid = tid >> 5;
    const int wm = wid >> 1, wn = wid & 1;    // 4x2 warps, each 32x32
    const int g = lane >> 2, t4 = lane & 3;
    const int m0 = blockIdx.y * 128, n0 = blockIdx.x * 64;

    float acc[2][4][4];
#pragma unroll
    for (int mt = 0; mt < 2; mt++)
#pragma unroll
        for (int nt = 0; nt < 4; nt++)
#pragma unroll
            for (int i = 0; i < 4; i++) acc[mt][nt][i] = 0.f;

    auto load_stage = [&](int buf, int kt) {
        int k0 = kt * 16;
#pragma unroll
        for (int i = 0; i < 2; i++) {
            int idx = tid + i * 256;
            int row = idx >> 2, c4 = (idx & 3) * 4;
            bool v = (m0 + row) < M;
            size_t off = (size_t)(v ? (m0 + row) : 0) * K2s + k0 + c4;
            cp_async16(&As0[(buf * 128 + row) * GPAD + c4], A0 + off, v);
            cp_async16(&As1[(buf * 128 + row) * GPAD + c4], A1 + off, v);
        }
        {
            int row = tid >> 2, c4 = (tid & 3) * 4;
            size_t off = (size_t)(n0 + row) * K2s + k0 + c4;
            cp_async16(&Bs0[(buf * 64 + row) * GPAD + c4], B0 + off, true);
            cp_async16(&Bs1[(buf * 64 + row) * GPAD + c4], B1 + off, true);
        }
        cp_async_commit();
    };

    auto compute = [&](int buf) {
#pragma unroll
        for (int sl = 0; sl < 2; sl++) {
            int ks = sl * 8;
            uint32_t a0[2][4], a1[2][4], b0[4][2], b1[4][2];
#pragma unroll
            for (int mt = 0; mt < 2; mt++) {
                int mr = buf * 128 + wm * 32 + mt * 16;
                a0[mt][0] = As0[(mr + g) * GPAD + ks + t4];
                a0[mt][1] = As0[(mr + g + 8) * GPAD + ks + t4];
                a0[mt][2] = As0[(mr + g) * GPAD + ks + t4 + 4];
                a0[mt][3] = As0[(mr + g + 8) * GPAD + ks + t4 + 4];
                a1[mt][0] = As1[(mr + g) * GPAD + ks + t4];
                a1[mt][1] = As1[(mr + g + 8) * GPAD + ks + t4];
                a1[mt][2] = As1[(mr + g) * GPAD + ks + t4 + 4];
                a1[mt][3] = As1[(mr + g + 8) * GPAD + ks + t4 + 4];
            }
#pragma unroll
            for (int nt = 0; nt < 4; nt++) {
                int nr = buf * 64 + wn * 32 + nt * 8 + g;
                b0[nt][0] = Bs0[nr * GPAD + ks + t4];
                b0[nt][1] = Bs0[nr * GPAD + ks + t4 + 4];
                b1[nt][0] = Bs1[nr * GPAD + ks + t4];
                b1[nt][1] = Bs1[nr * GPAD + ks + t4 + 4];
            }
#pragma unroll
            for (int mt = 0; mt < 2; mt++)
#pragma unroll
                for (int nt = 0; nt < 4; nt++) {
                    mma_bf16(acc[mt][nt], a0[mt], b0[nt]);  // hi*hi
                    mma_bf16(acc[mt][nt], a0[mt], b1[nt]);  // hi*lo
                    mma_bf16(acc[mt][nt], a1[mt], b0[nt]);  // lo*hi
                }
        }
    };

    const int kTiles = K2len / 16;
    load_stage(0, 0);
    int buf = 0;
    for (int kt = 0; kt < kTiles; kt++) {
        if (kt + 1 < kTiles) {
            load_stage(buf ^ 1, kt + 1);
            cp_async_wait<1>();
        } else {
            cp_async_wait<0>();
        }
        __syncthreads();
        compute(buf);
        __syncthreads();
        buf ^= 1;
    }

#pragma unroll
    for (int mt = 0; mt < 2; mt++) {
#pragma unroll
        for (int nt = 0; nt < 4; nt++) {
            int gc = n0 + wn * 32 + nt * 8 + t4 * 2;
            float b0v = bias ? bias[gc] : 0.f;
            float b1v = bias ? bias[gc + 1] : 0.f;
            int gr0 = m0 + wm * 32 + mt * 16 + g;
            if (gr0 < M) {
                float2 o = make_float2(acc[mt][nt][0] + b0v, acc[mt][nt][1] + b1v);
                *(float2*)(Cm + (size_t)gr0 * N + gc) = o;
            }
            int gr1 = gr0 + 8;
            if (gr1 < M) {
                float2 o = make_float2(acc[mt][nt][2] + b0v, acc[mt][nt][3] + b1v);
                *(float2*)(Cm + (size_t)gr1 * N + gc) = o;
            }
        }
    }
}

// ---------------- layernorm: plain + packed bf16 outputs ----------------
__device__ __forceinline__ float block_reduce_sum(float v, float* sh) {
    int lane = threadIdx.x & 31, warp = threadIdx.x >> 5;
#pragma unroll
    for (int o = 16; o; o >>= 1) v += __shfl_xor_sync(0xffffffffu, v, o);
    if (lane == 0) sh[warp] = v;
    __syncthreads();
    if (warp == 0) {
        float t = (lane < 8) ? sh[lane] : 0.f;
#pragma unroll
        for (int o = 4; o; o >>= 1) t += __shfl_xor_sync(0xffffffffu, t, o);
        if (lane == 0) sh[0] = t;
    }
    __syncthreads();
    float r = sh[0];
    __syncthreads();
    return r;
}

__global__ void ln_kernel(const float* __restrict__ in, const float* __restrict__ resid,
                          const float* __restrict__ g, const float* __restrict__ bb,
                          float* __restrict__ out, uint32_t* __restrict__ p0,
                          uint32_t* __restrict__ p1) {
    __shared__ float sh[32];
    int row = blockIdx.x, tid = threadIdx.x;  // 256 threads, 2 adjacent cols each
    size_t base = (size_t)row * 512;
    float2 x = *(const float2*)&in[base + 2 * tid];
    if (resid) {
        float2 r = *(const float2*)&resid[base + 2 * tid];
        x.x += r.x; x.y += r.y;
    }
    float mu = block_reduce_sum(x.x + x.y, sh) * (1.f / 512.f);
    float d0 = x.x - mu, d1 = x.y - mu;
    float var = block_reduce_sum(d0 * d0 + d1 * d1, sh) * (1.f / 512.f);
    float rstd = rsqrtf(var + 1e-5f);
    float2 gv = *(const float2*)&g[2 * tid];
    float2 bv = *(const float2*)&bb[2 * tid];
    float y0 = d0 * rstd * gv.x + bv.x;
    float y1 = d1 * rstd * gv.y + bv.y;
    *(float2*)&out[base + 2 * tid] = make_float2(y0, y1);
    uint32_t w0, w1;
    pack_pair(y0, y1, w0, w1);
    p0[(size_t)row * 256 + tid] = w0;
    p1[(size_t)row * 256 + tid] = w1;
}

// ---------------- attention: smem-staged K/V, one block per (b,h) ----------------
// smem layout (floats): Ks[64][229], Vs[225][68], qs[16*64], sc[16][228]
constexpr int ATT_KS = 64 * 229;
constexpr int ATT_VS = 225 * 68;
constexpr int ATT_QS = 16 * 64;
constexpr int ATT_SC = 16 * 228;
constexpr int ATT_SMEM_BYTES = (ATT_KS + ATT_VS + ATT_QS + ATT_SC) * 4;  // ~138.5 KB

__global__ __launch_bounds__(256) void attn_kernel() {
    extern __shared__ float smf[];
    float* Ks = smf;                 // [d][l] transposed, pad 229
    float* Vs = Ks + ATT_KS;         // [l][d] pad 68
    float* qs = Vs + ATT_VS;         // [p*64+d]
    float* sc = qs + ATT_QS;         // [p*228+l]
    int bh = blockIdx.x;
    int b = bh >> 3, h = bh & 7;
    int tid = threadIdx.x;  // 256

    for (int i = tid; i < 1024; i += 256)
        qs[i] = g_QKV[(size_t)(b * 16 + (i >> 6)) * 1536 + h * 64 + (i & 63)];
    // cooperative coalesced K/V loads
    for (int i = tid; i < 225 * 64; i += 256) {
        int l = i >> 6, d = i & 63;
        const float* row = g_QKV + (size_t)(kPatchRows + b * kL + l) * 1536 + h * 64 + d;
        Ks[d * 229 + l] = row[512];
        Vs[l * 68 + d] = row[1024];
    }
    __syncthreads();

    // scores: thread -> (p,l)
    for (int idx = tid; idx < 16 * 225; idx += 256) {
        int p = idx / 225, l = idx - p * 225;
        float s = 0.f;
#pragma unroll
        for (int d = 0; d < 64; d++) s += qs[p * 64 + d] * Ks[d * 229 + l];
        sc[p * 228 + l] = s * 0.125f;
    }
    __syncthreads();

    int warp = tid >> 5, lane = tid & 31;
    for (int p = warp; p < 16; p += 8) {
        float mx = -1e30f;
        for (int l = lane; l < 225; l += 32) mx = fmaxf(mx, sc[p * 228 + l]);
#pragma unroll
        for (int o = 16; o; o >>= 1) mx = fmaxf(mx, __shfl_xor_sync(0xffffffffu, mx, o));
        float sum = 0.f;
        for (int l = lane; l < 225; l += 32) {
            float e = __expf(sc[p * 228 + l] - mx);
            sc[p * 228 + l] = e;
            sum += e;
        }
#pragma unroll
        for (int o = 16; o; o >>= 1) sum += __shfl_xor_sync(0xffffffffu, sum, o);
        float inv = 1.f / sum;
        for (int l = lane; l < 225; l += 32) sc[p * 228 + l] *= inv;
    }
    __syncthreads();

    // output (packed bf16 pairs over adjacent d): thread -> (p, d2)
    for (int i = tid; i < 512; i += 256) {
        int p = i >> 5, d2 = i & 31;
        float s0 = 0.f, s1 = 0.f;
        const float* sp = sc + p * 228;
        const float* vp = Vs + 2 * d2;
        for (int l = 0; l < 225; l++) {
            float2 v = *(const float2*)(vp + l * 68);
            float w = sp[l];
            s0 += w * v.x;
            s1 += w * v.y;
        }
        uint32_t w0, w1;
        pack_pair(s0, s1, w0, w1);
        size_t oi = (size_t)(b * 16 + p) * 256 + h * 32 + d2;
        g_attnp0[oi] = w0;
        g_attnp1[oi] = w1;
    }
}

// ---------------- MLP epilogue ----------------
__global__ void gelu_res_kernel() {
    int i = blockIdx.x * blockDim.x + threadIdx.x;
    if (i >= kPatchRows * kE) return;
    float hv = g_hid[i];
    g_xm[i] = 0.5f * hv * (1.f + erff(hv * 0.70710678118654752f)) + g_res[i];
}

__global__ void outs_kernel(const float* __restrict__ Wc, const float* __restrict__ bc) {
    int t = threadIdx.x;  // 256 = 128 rows x 2
    int row = t >> 1, j = t & 1;
    const float* x = g_xm + (size_t)row * 512;
    const float* w = Wc + j * 512;
    float s = 0.f;
    for (int k = 0; k < 512; k++) s += x[k] * w[k];
    g_outs[row * 2 + j] = s + bc[j];
}

// ---------------- segment mean + final scatter ----------------
__global__ void zero_seg_kernel() {
    int t = threadIdx.x;
    if (t < kB * 17 * 3) g_sums[t] = 0.f;
    if (t < kB * 17) g_cnt[t] = 0.f;
}

__global__ void seg_kernel(const float* __restrict__ probs, const int* __restrict__ masks) {
    __shared__ float ssum[51];
    __shared__ float scnt[17];
    int t = threadIdx.x;  // 256
    if (t < 51) ssum[t] = 0.f;
    if (t < 17) scnt[t] = 0.f;
    __syncthreads();
    int b = blockIdx.x >> 6;
    int chunk = blockIdx.x & 63;
    int base = chunk * 1024;
#pragma unroll
    for (int k = 0; k < 4; k++) {
        int pix = base + k * 256 + t;
        int lab = masks[b * 65536 + pix];
        atomicAdd(&scnt[lab], 1.f);
#pragma unroll
        for (int c = 0; c < 3; c++)
            atomicAdd(&ssum[lab * 3 + c], probs[((size_t)(b * 3 + c)) * 65536 + pix]);
    }
    __syncthreads();
    if (t < 51) atomicAdd(&g_sums[b * 51 + t], ssum[t]);
    if (t < 17) atomicAdd(&g_cnt[b * 17 + t], scnt[t]);
}

__global__ void newv_kernel() {
    int t = threadIdx.x;  // 128
    if (t < 24) { int b = t / 3, c = t % 3; g_newv[b * 51 + c] = 0.f; }
    int b = t >> 4, p = t & 15, lab = p + 1;
    float denom = fmaxf(g_cnt[b * 17 + lab], 1.f);
    float m0 = g_sums[(b * 17 + lab) * 3 + 0] / denom + 1e-6f;
    float m1 = g_sums[(b * 17 + lab) * 3 + 1] / denom + 1e-6f;
    float m2 = g_sums[(b * 17 + lab) * 3 + 2] / denom + 1e-6f;
    float o0 = g_outs[(b * 16 + p) * 2 + 0], o1 = g_outs[(b * 16 + p) * 2 + 1];
    float n0 = m0 / (0.5f * (m1 + m2)) * (0.5f * (o0 + o1));
    g_newv[(b * 17 + lab) * 3 + 0] = n0;
    g_newv[(b * 17 + lab) * 3 + 1] = o0;
    g_newv[(b * 17 + lab) * 3 + 2] = o1;
}

__global__ void scatter_kernel(const float* __restrict__ probs, const int* __restrict__ masks,
                               float* __restrict__ out) {
    int i = blockIdx.x * blockDim.x + threadIdx.x;
    if (i >= kB * 65536) return;
    int b = i >> 16, pix = i & 65535;
    int lab = masks[i];
#pragma unroll
    for (int c = 0; c < 3; c++) {
        size_t o = ((size_t)(b * 3 + c)) * 65536 + pix;
        out[o] = (lab > 0) ? g_newv[(b * 17 + lab) * 3 + c] : probs[o];
    }
}

// ---------------- launch ----------------
extern "C" void kernel_launch(void* const* d_in, const int* /*in_sizes*/, int /*n_in*/,
                              void* d_out, int /*out_size*/) {
    const float* features = (const float*)d_in[0];
    const float* probs    = (const float*)d_in[1];
    const float* patches  = (const float*)d_in[2];
    const int*   masks    = (const int*)d_in[3];
    const float* ln_g = (const float*)d_in[4];
    const float* ln_b = (const float*)d_in[5];
    const float* Wr   = (const float*)d_in[6];
    const float* br   = (const float*)d_in[7];
    const float* Wqkv = (const float*)d_in[8];
    const float* bqkv = (const float*)d_in[9];
    const float* Wo   = (const float*)d_in[10];
    const float* bo   = (const float*)d_in[11];
    const float* Wm   = (const float*)d_in[12];
    const float* bm   = (const float*)d_in[13];
    const float* Wc   = (const float*)d_in[14];
    const float* bc   = (const float*)d_in[15];
    float* out = (float*)d_out;

    cudaFuncSetAttribute(gemm_bf16_kernel, cudaFuncAttributeMaxDynamicSharedMemorySize,
                         GEMM_SMEM_BYTES);
    cudaFuncSetAttribute(attn_kernel, cudaFuncAttributeMaxDynamicSharedMemorySize,
                         ATT_SMEM_BYTES);

    uint32_t *pXp0, *pXp1, *pWrp0, *pWrp1, *pWqkvp0, *pWqkvp1, *pWop0, *pWop1, *pWmp0, *pWmp1;
    uint32_t *pYnp0, *pYnp1, *pAttnp0, *pAttnp1, *pResp0, *pResp1;
    float *pY, *pY2, *pYn, *pQKV, *pProj, *pRes, *pHid;
    cudaGetSymbolAddress((void**)&pXp0, g_Xp0);
    cudaGetSymbolAddress((void**)&pXp1, g_Xp1);
    cudaGetSymbolAddress((void**)&pWrp0, g_Wrp0);
    cudaGetSymbolAddress((void**)&pWrp1, g_Wrp1);
    cudaGetSymbolAddress((void**)&pWqkvp0, g_Wqkvp0);
    cudaGetSymbolAddress((void**)&pWqkvp1, g_Wqkvp1);
    cudaGetSymbolAddress((void**)&pWop0, g_Wop0);
    cudaGetSymbolAddress((void**)&pWop1, g_Wop1);
    cudaGetSymbolAddress((void**)&pWmp0, g_Wmp0);
    cudaGetSymbolAddress((void**)&pWmp1, g_Wmp1);
    cudaGetSymbolAddress((void**)&pYnp0, g_Ynp0);
    cudaGetSymbolAddress((void**)&pYnp1, g_Ynp1);
    cudaGetSymbolAddress((void**)&pAttnp0, g_attnp0);
    cudaGetSymbolAddress((void**)&pAttnp1, g_attnp1);
    cudaGetSymbolAddress((void**)&pResp0, g_resp0);
    cudaGetSymbolAddress((void**)&pResp1, g_resp1);
    cudaGetSymbolAddress((void**)&pY, g_Y);
    cudaGetSymbolAddress((void**)&pY2, g_Y2);
    cudaGetSymbolAddress((void**)&pYn, g_Yn);
    cudaGetSymbolAddress((void**)&pQKV, g_QKV);
    cudaGetSymbolAddress((void**)&pProj, g_proj);
    cudaGetSymbolAddress((void**)&pRes, g_res);
    cudaGetSymbolAddress((void**)&pHid, g_hid);

    // producers (pre-split everything)
    pool_features_kernel<<<(kB * 16 * 128 * 128) / 256, 256>>>(features);
    pool_patches_kernel<<<(kPatchRows * (kFV / 2)) / 256, 256>>>(patches);
    gather_blocks_kernel<<<(kB * kL * (kFV / 2)) / 256, 256>>>();
    split_weight_kernel<<<(kE * kFV / 2) / 256, 256>>>(Wr, pWrp0, pWrp1, kE * kFV / 2);
    split_weight_kernel<<<(3 * kE * kE / 2) / 256, 256>>>(Wqkv, pWqkvp0, pWqkvp1, 3 * kE * kE / 2);
    split_weight_kernel<<<(kE * kE / 2) / 256, 256>>>(Wo, pWop0, pWop1, kE * kE / 2);
    split_weight_kernel<<<(kE * kE / 2) / 256, 256>>>(Wm, pWmp0, pWmp1, kE * kE / 2);

    // patch2vec: split-K=2 -> two half-K GEMMs, summed inside the next LN
    constexpr int K2full = kFV / 2;    // 2048
    constexpr int K2half = K2full / 2; // 1024
    gemm_bf16_kernel<<<dim3(512 / 64, (kRows + 127) / 128), 256, GEMM_SMEM_BYTES>>>(
        pXp0, pXp1, pWrp0, pWrp1, br, pY, kRows, 512, K2half, K2full);
    gemm_bf16_kernel<<<dim3(512 / 64, (kRows + 127) / 128), 256, GEMM_SMEM_BYTES>>>(
        pXp0 + K2half, pXp1 + K2half, pWrp0 + K2half, pWrp1 + K2half, nullptr, pY2,
        kRows, 512, K2half, K2full);
    ln_kernel<<<kRows, 256>>>(pY, pY2, ln_g, ln_b, pYn, pYnp0, pYnp1);

    // fused QKV: (1928,512)@(512,1536)^T
    gemm_bf16_kernel<<<dim3(1536 / 64, (kRows + 127) / 128), 256, GEMM_SMEM_BYTES>>>(
        pYnp0, pYnp1, pWqkvp0, pWqkvp1, bqkv, pQKV, kRows, 1536, kE / 2, kE / 2);
    attn_kernel<<<kB * kNH, 256, ATT_SMEM_BYTES>>>();

    // out proj + residual LN
    gemm_bf16_kernel<<<dim3(512 / 64, 1), 256, GEMM_SMEM_BYTES>>>(
        pAttnp0, pAttnp1, pWop0, pWop1, bo, pProj, kPatchRows, 512, kE / 2, kE / 2);
    ln_kernel<<<kPatchRows, 256>>>(pProj, pYn, ln_g, ln_b, pRes, pResp0, pResp1);

    // MLP
    gemm_bf16_kernel<<<dim3(512 / 64, 1), 256, GEMM_SMEM_BYTES>>>(
        pResp0, pResp1, pWmp0, pWmp1, bm, pHid, kPatchRows, 512, kE / 2, kE / 2);
    gelu_res_kernel<<<(kPatchRows * kE) / 256, 256>>>();
    outs_kernel<<<1, 256>>>(Wc, bc);

    // segment statistics + final output
    zero_seg_kernel<<<1, 512>>>();
    seg_kernel<<<kB * 64, 256>>>(probs, masks);
    newv_kernel<<<1, 128>>>();
    scatter_kernel<<<(kB * 65536) / 256, 256>>>(probs, masks, out);
}

// round 8
// speedup vs baseline: 2.7536x; 1.0747x over previous
#include <cuda_runtime.h>
#include <cuda_bf16.h>
#include <math.h>
#include <stdint.h>

// ---------------- problem constants ----------------
constexpr int kB = 8, kC = 64, kH = 256, kW = 256;
constexpr int kE = 512, kNH = 8, kHD = 64;
constexpr int kP = 16, kN = 15, kL = 225;      // n=15 windows, L=225 blocks/img
constexpr int kFV = 4096;                       // 16 ch-groups * 16 * 16
constexpr int kRows = kB * (kP + kL);           // 1928 rows
constexpr int kPatchRows = kB * kP;             // 128

// ---------------- device scratch ----------------
// pre-split bf16 planes, packed as u32 of 2 adjacent-K bf16
__device__ uint32_t g_Xp0[kRows * (kFV / 2)];
__device__ uint32_t g_Xp1[kRows * (kFV / 2)];
__device__ uint32_t g_Wrp0[kE * (kFV / 2)], g_Wrp1[kE * (kFV / 2)];
__device__ uint32_t g_Wqkvp0[3 * kE * (kE / 2)], g_Wqkvp1[3 * kE * (kE / 2)];
__device__ uint32_t g_Wop0[kE * (kE / 2)], g_Wop1[kE * (kE / 2)];
__device__ uint32_t g_Wmp0[kE * (kE / 2)], g_Wmp1[kE * (kE / 2)];
__device__ uint32_t g_Ynp0[kRows * (kE / 2)], g_Ynp1[kRows * (kE / 2)];
__device__ uint32_t g_attnp0[kPatchRows * (kE / 2)], g_attnp1[kPatchRows * (kE / 2)];
__device__ uint32_t g_resp0[kPatchRows * (kE / 2)], g_resp1[kPatchRows * (kE / 2)];

__device__ float g_Y[kRows * kE];
__device__ float g_Y2[kRows * kE];   // split-K partial
__device__ float g_Yn[kRows * kE];
__device__ float g_QKV[kRows * 3 * kE];
__device__ float g_proj[kPatchRows * kE];
__device__ float g_res[kPatchRows * kE];
__device__ float g_hid[kPatchRows * kE];
__device__ float g_xm[kPatchRows * kE];
__device__ float g_outs[kPatchRows * 2];
__device__ float g_sums[kB * 17 * 3];
__device__ float g_cnt[kB * 17];
__device__ float g_newv[kB * 17 * 3];

// ---------------- bf16 split/pack ----------------
__device__ __forceinline__ void pack_pair(float x0, float x1, uint32_t& w0, uint32_t& w1) {
    __nv_bfloat162 h = __floats2bfloat162_rn(x0, x1);
    float r0 = x0 - __low2float(h);
    float r1 = x1 - __high2float(h);
    __nv_bfloat162 l = __floats2bfloat162_rn(r0, r1);
    w0 = *reinterpret_cast<uint32_t*>(&h);
    w1 = *reinterpret_cast<uint32_t*>(&l);
}

// ---------------- fused pooling + window scatter ----------------
// One thread handles a PAIR of adjacent pooled x positions (2xp, 2xp+1) for
// (b, cg, y). Packs once and writes to every block row (li,lj) that uses it.
// Each (row, v2) destination has exactly one source -> deterministic.
__global__ void pool_features_fused_kernel(const float* __restrict__ f) {
    int i = blockIdx.x * blockDim.x + threadIdx.x;
    if (i >= kB * 16 * 128 * 64) return;
    int xp = i & 63, y = (i >> 6) & 127, cg = (i >> 13) & 15, b = i >> 17;
    float s0 = 0.f, s1 = 0.f;
#pragma unroll
    for (int cc = 0; cc < 4; cc++) {
        const float* base = f + ((size_t)(b * kC + cg * 4 + cc) * kH + 2 * y) * kW + 4 * xp;
#pragma unroll
        for (int dy = 0; dy < 2; dy++) {
            float4 q = *(const float4*)(base + dy * kW);
            s0 += q.x + q.y;
            s1 += q.z + q.w;
        }
    }
    uint32_t w0, w1;
    pack_pair(s0 * (1.f / 16.f), s1 * (1.f / 16.f), w0, w1);
#pragma unroll
    for (int dli = 0; dli < 2; dli++) {
        int li = (y >> 3) - dli;
        if (li < 0 || li > 14) continue;
        int hh = y - 8 * li;           // 0..15 by construction
#pragma unroll
        for (int dlj = 0; dlj < 2; dlj++) {
            int lj = (xp >> 2) - dlj;
            if (lj < 0 || lj > 14) continue;
            int w2 = xp - 4 * lj;      // 0..7 by construction
            size_t idx = (size_t)(kPatchRows + b * kL + li * kN + lj) * 2048 +
                         cg * 128 + hh * 8 + w2;
            g_Xp0[idx] = w0;
            g_Xp1[idx] = w1;
        }
    }
}

// patches -> Xp rows [0,128)
__global__ void pool_patches_kernel(const float* __restrict__ p) {
    int i = blockIdx.x * blockDim.x + threadIdx.x;
    if (i >= kPatchRows * (kFV / 2)) return;
    int v2 = i & 2047, n = i >> 11;
    int w2 = v2 & 7, hh = (v2 >> 3) & 15, cg = v2 >> 7;
    float s0 = 0.f, s1 = 0.f;
#pragma unroll
    for (int cc = 0; cc < 4; cc++) {
        const float* base = p + (size_t)n * 65536 + (cg * 4 + cc) * 1024 + 4 * w2;
#pragma unroll
        for (int dh = 0; dh < 2; dh++) {
            float4 q = *(const float4*)(base + (2 * hh + dh) * 32);
            s0 += q.x + q.y;
            s1 += q.z + q.w;
        }
    }
    uint32_t w0, w1;
    pack_pair(s0 * (1.f / 16.f), s1 * (1.f / 16.f), w0, w1);
    g_Xp0[(size_t)n * 2048 + v2] = w0;
    g_Xp1[(size_t)n * 2048 + v2] = w1;
}

__global__ void split_weight_kernel(const float* __restrict__ W, uint32_t* __restrict__ P0,
                                    uint32_t* __restrict__ P1, int total2) {
    int i = blockIdx.x * blockDim.x + threadIdx.x;
    if (i >= total2) return;
    float2 x = *(const float2*)&W[2 * i];
    uint32_t w0, w1;
    pack_pair(x.x, x.y, w0, w1);
    P0[i] = w0;
    P1[i] = w1;
}

// batched split of the three K=512 weights
__global__ void split_weight3_kernel(const float* __restrict__ W1, const float* __restrict__ W2,
                                     const float* __restrict__ W3,
                                     uint32_t* __restrict__ P10, uint32_t* __restrict__ P11,
                                     uint32_t* __restrict__ P20, uint32_t* __restrict__ P21,
                                     uint32_t* __restrict__ P30, uint32_t* __restrict__ P31) {
    const int n1 = 3 * kE * kE / 2, n2 = kE * kE / 2;
    int i = blockIdx.x * blockDim.x + threadIdx.x;
    const float* W;
    uint32_t *P0, *P1;
    int j;
    if (i < n1) { W = W1; P0 = P10; P1 = P11; j = i; }
    else if (i < n1 + n2) { W = W2; P0 = P20; P1 = P21; j = i - n1; }
    else if (i < n1 + 2 * n2) { W = W3; P0 = P30; P1 = P31; j = i - n1 - n2; }
    else return;
    float2 x = *(const float2*)&W[2 * j];
    uint32_t w0, w1;
    pack_pair(x.x, x.y, w0, w1);
    P0[j] = w0;
    P1[j] = w1;
}

// ---------------- bf16x2 (3-mma) tensor GEMM ----------------
__device__ __forceinline__ void mma_bf16(float* d, const uint32_t* a, const uint32_t* b) {
    asm volatile(
        "mma.sync.aligned.m16n8k16.row.col.f32.bf16.bf16.f32 "
        "{%0,%1,%2,%3}, {%4,%5,%6,%7}, {%8,%9}, {%0,%1,%2,%3};"
        : "+f"(d[0]), "+f"(d[1]), "+f"(d[2]), "+f"(d[3])
        : "r"(a[0]), "r"(a[1]), "r"(a[2]), "r"(a[3]), "r"(b[0]), "r"(b[1]));
}

__device__ __forceinline__ void cp_async16(void* smem, const void* g, bool valid) {
    uint32_t s = (uint32_t)__cvta_generic_to_shared(smem);
    int sz = valid ? 16 : 0;
    asm volatile("cp.async.cg.shared.global [%0], [%1], 16, %2;\n" :: "r"(s), "l"(g), "r"(sz));
}
__device__ __forceinline__ void cp_commit() { asm volatile("cp.async.commit_group;" ::: "memory"); }
template <int NN>
__device__ __forceinline__ void cp_wait() { asm volatile("cp.async.wait_group %0;" :: "n"(NN)); }

// 20 u32 = 80 B row stride: 16B-aligned for cp.async, conflict-free fragment LDS.
constexpr int GPAD = 20;
constexpr int GEMM_SMEM_BYTES = (2 * 128 * GPAD * 2 + 2 * 64 * GPAD * 2) * 4;  // 61,440

// C[M,N] = A@Bw^T (+bias). blockIdx.z==1 selects the second K-half (offset
// K2len words) and writes the partial to Cm2 without bias (summed in next LN).
__global__ __launch_bounds__(256) void gemm_bf16_kernel(
    const uint32_t* __restrict__ A0, const uint32_t* __restrict__ A1,
    const uint32_t* __restrict__ B0, const uint32_t* __restrict__ B1,
    const float* __restrict__ bias, float* __restrict__ Cm, float* __restrict__ Cm2,
    int M, int N, int K2len, int K2s)
{
    if (blockIdx.z == 1) {
        A0 += K2len; A1 += K2len; B0 += K2len; B1 += K2len;
        Cm = Cm2;
        bias = nullptr;
    }
    extern __shared__ uint32_t sm[];
    uint32_t* As0 = sm;
    uint32_t* As1 = As0 + 2 * 128 * GPAD;
    uint32_t* Bs0 = As1 + 2 * 128 * GPAD;
    uint32_t* Bs1 = Bs0 + 2 * 64 * GPAD;

    const int tid = threadIdx.x;
    const int lane = tid & 31, wid = tid >> 5;
    const int wm = wid >> 1, wn = wid & 1;
    const int g = lane >> 2, t4 = lane & 3;
    const int m0 = blockIdx.y * 128, n0 = blockIdx.x * 64;

    float acc[2][4][4];
#pragma unroll
    for (int mt = 0; mt < 2; mt++)
#pragma unroll
        for (int nt = 0; nt < 4; nt++)
#pragma unroll
            for (int i = 0; i < 4; i++) acc[mt][nt][i] = 0.f;

    auto load_stage = [&](int buf, int kt) {
        int k0 = kt * 16;
#pragma unroll
        for (int i = 0; i < 2; i++) {
            int idx = tid + i * 256;
            int row = idx >> 2, c4 = (idx & 3) * 4;
            bool v = (m0 + row) < M;
            size_t off = (size_t)(v ? (m0 + row) : 0) * K2s + k0 + c4;
            cp_async16(&As0[(buf * 128 + row) * GPAD + c4], A0 + off, v);
            cp_async16(&As1[(buf * 128 + row) * GPAD + c4], A1 + off, v);
        }
        {
            int row = tid >> 2, c4 = (tid & 3) * 4;
            size_t off = (size_t)(n0 + row) * K2s + k0 + c4;
            cp_async16(&Bs0[(buf * 64 + row) * GPAD + c4], B0 + off, true);
            cp_async16(&Bs1[(buf * 64 + row) * GPAD + c4], B1 + off, true);
        }
        cp_commit();
    };

    auto compute = [&](int buf) {
#pragma unroll
        for (int sl = 0; sl < 2; sl++) {
            int ks = sl * 8;
            uint32_t a0[2][4], a1[2][4], b0[4][2], b1[4][2];
#pragma unroll
            for (int mt = 0; mt < 2; mt++) {
                int mr = buf * 128 + wm * 32 + mt * 16;
                a0[mt][0] = As0[(mr + g) * GPAD + ks + t4];
                a0[mt][1] = As0[(mr + g + 8) * GPAD + ks + t4];
                a0[mt][2] = As0[(mr + g) * GPAD + ks + t4 + 4];
                a0[mt][3] = As0[(mr + g + 8) * GPAD + ks + t4 + 4];
                a1[mt][0] = As1[(mr + g) * GPAD + ks + t4];
                a1[mt][1] = As1[(mr + g + 8) * GPAD + ks + t4];
                a1[mt][2] = As1[(mr + g) * GPAD + ks + t4 + 4];
                a1[mt][3] = As1[(mr + g + 8) * GPAD + ks + t4 + 4];
            }
#pragma unroll
            for (int nt = 0; nt < 4; nt++) {
                int nr = buf * 64 + wn * 32 + nt * 8 + g;
                b0[nt][0] = Bs0[nr * GPAD + ks + t4];
                b0[nt][1] = Bs0[nr * GPAD + ks + t4 + 4];
                b1[nt][0] = Bs1[nr * GPAD + ks + t4];
                b1[nt][1] = Bs1[nr * GPAD + ks + t4 + 4];
            }
#pragma unroll
            for (int mt = 0; mt < 2; mt++)
#pragma unroll
                for (int nt = 0; nt < 4; nt++) {
                    mma_bf16(acc[mt][nt], a0[mt], b0[nt]);
                    mma_bf16(acc[mt][nt], a0[mt], b1[nt]);
                    mma_bf16(acc[mt][nt], a1[mt], b0[nt]);
                }
        }
    };

    const int kTiles = K2len / 16;
    load_stage(0, 0);
    int buf = 0;
    for (int kt = 0; kt < kTiles; kt++) {
        if (kt + 1 < kTiles) {
            load_stage(buf ^ 1, kt + 1);
            cp_wait<1>();
        } else {
            cp_wait<0>();
        }
        __syncthreads();
        compute(buf);
        __syncthreads();
        buf ^= 1;
    }

#pragma unroll
    for (int mt = 0; mt < 2; mt++) {
#pragma unroll
        for (int nt = 0; nt < 4; nt++) {
            int gc = n0 + wn * 32 + nt * 8 + t4 * 2;
            float b0v = bias ? bias[gc] : 0.f;
            float b1v = bias ? bias[gc + 1] : 0.f;
            int gr0 = m0 + wm * 32 + mt * 16 + g;
            if (gr0 < M) {
                float2 o = make_float2(acc[mt][nt][0] + b0v, acc[mt][nt][1] + b1v);
                *(float2*)(Cm + (size_t)gr0 * N + gc) = o;
            }
            int gr1 = gr0 + 8;
            if (gr1 < M) {
                float2 o = make_float2(acc[mt][nt][2] + b0v, acc[mt][nt][3] + b1v);
                *(float2*)(Cm + (size_t)gr1 * N + gc) = o;
            }
        }
    }
}

// ---------------- layernorm: plain + packed bf16 outputs ----------------
__device__ __forceinline__ float block_reduce_sum(float v, float* sh) {
    int lane = threadIdx.x & 31, warp = threadIdx.x >> 5;
#pragma unroll
    for (int o = 16; o; o >>= 1) v += __shfl_xor_sync(0xffffffffu, v, o);
    if (lane == 0) sh[warp] = v;
    __syncthreads();
    if (warp == 0) {
        float t = (lane < 8) ? sh[lane] : 0.f;
#pragma unroll
        for (int o = 4; o; o >>= 1) t += __shfl_xor_sync(0xffffffffu, t, o);
        if (lane == 0) sh[0] = t;
    }
    __syncthreads();
    float r = sh[0];
    __syncthreads();
    return r;
}

__global__ void ln_kernel(const float* __restrict__ in, const float* __restrict__ resid,
                          const float* __restrict__ g, const float* __restrict__ bb,
                          float* __restrict__ out, uint32_t* __restrict__ p0,
                          uint32_t* __restrict__ p1) {
    __shared__ float sh[32];
    int row = blockIdx.x, tid = threadIdx.x;
    size_t base = (size_t)row * 512;
    float2 x = *(const float2*)&in[base + 2 * tid];
    if (resid) {
        float2 r = *(const float2*)&resid[base + 2 * tid];
        x.x += r.x; x.y += r.y;
    }
    float mu = block_reduce_sum(x.x + x.y, sh) * (1.f / 512.f);
    float d0 = x.x - mu, d1 = x.y - mu;
    float var = block_reduce_sum(d0 * d0 + d1 * d1, sh) * (1.f / 512.f);
    float rstd = rsqrtf(var + 1e-5f);
    float2 gv = *(const float2*)&g[2 * tid];
    float2 bv = *(const float2*)&bb[2 * tid];
    float y0 = d0 * rstd * gv.x + bv.x;
    float y1 = d1 * rstd * gv.y + bv.y;
    *(float2*)&out[base + 2 * tid] = make_float2(y0, y1);
    uint32_t w0, w1;
    pack_pair(y0, y1, w0, w1);
    p0[(size_t)row * 256 + tid] = w0;
    p1[(size_t)row * 256 + tid] = w1;
}

// ---------------- attention: smem-staged K/V ----------------
constexpr int ATT_KS = 64 * 229;
constexpr int ATT_VS = 225 * 68;
constexpr int ATT_QS = 16 * 64;
constexpr int ATT_SC = 16 * 228;
constexpr int ATT_SMEM_BYTES = (ATT_KS + ATT_VS + ATT_QS + ATT_SC) * 4;

__global__ __launch_bounds__(256) void attn_kernel() {
    extern __shared__ float smf[];
    float* Ks = smf;
    float* Vs = Ks + ATT_KS;
    float* qs = Vs + ATT_VS;
    float* sc = qs + ATT_QS;
    int bh = blockIdx.x;
    int b = bh >> 3, h = bh & 7;
    int tid = threadIdx.x;

    for (int i = tid; i < 1024; i += 256)
        qs[i] = g_QKV[(size_t)(b * 16 + (i >> 6)) * 1536 + h * 64 + (i & 63)];
    for (int i = tid; i < 225 * 64; i += 256) {
        int l = i >> 6, d = i & 63;
        const float* row = g_QKV + (size_t)(kPatchRows + b * kL + l) * 1536 + h * 64 + d;
        Ks[d * 229 + l] = row[512];
        Vs[l * 68 + d] = row[1024];
    }
    __syncthreads();

    for (int idx = tid; idx < 16 * 225; idx += 256) {
        int p = idx / 225, l = idx - p * 225;
        float s = 0.f;
#pragma unroll
        for (int d = 0; d < 64; d++) s += qs[p * 64 + d] * Ks[d * 229 + l];
        sc[p * 228 + l] = s * 0.125f;
    }
    __syncthreads();

    int warp = tid >> 5, lane = tid & 31;
    for (int p = warp; p < 16; p += 8) {
        float mx = -1e30f;
        for (int l = lane; l < 225; l += 32) mx = fmaxf(mx, sc[p * 228 + l]);
#pragma unroll
        for (int o = 16; o; o >>= 1) mx = fmaxf(mx, __shfl_xor_sync(0xffffffffu, mx, o));
        float sum = 0.f;
        for (int l = lane; l < 225; l += 32) {
            float e = __expf(sc[p * 228 + l] - mx);
            sc[p * 228 + l] = e;
            sum += e;
        }
#pragma unroll
        for (int o = 16; o; o >>= 1) sum += __shfl_xor_sync(0xffffffffu, sum, o);
        float inv = 1.f / sum;
        for (int l = lane; l < 225; l += 32) sc[p * 228 + l] *= inv;
    }
    __syncthreads();

    for (int i = tid; i < 512; i += 256) {
        int p = i >> 5, d2 = i & 31;
        float s0 = 0.f, s1 = 0.f;
        const float* sp = sc + p * 228;
        const float* vp = Vs + 2 * d2;
        for (int l = 0; l < 225; l++) {
            float2 v = *(const float2*)(vp + l * 68);
            float w = sp[l];
            s0 += w * v.x;
            s1 += w * v.y;
        }
        uint32_t w0, w1;
        pack_pair(s0, s1, w0, w1);
        size_t oi = (size_t)(b * 16 + p) * 256 + h * 32 + d2;
        g_attnp0[oi] = w0;
        g_attnp1[oi] = w1;
    }
}

// ---------------- MLP epilogue ----------------
__global__ void gelu_res_kernel() {
    int i = blockIdx.x * blockDim.x + threadIdx.x;
    if (i >= kPatchRows * kE) return;
    float hv = g_hid[i];
    g_xm[i] = 0.5f * hv * (1.f + erff(hv * 0.70710678118654752f)) + g_res[i];
}

__global__ void outs_kernel(const float* __restrict__ Wc, const float* __restrict__ bc) {
    int t = threadIdx.x;
    int row = t >> 1, j = t & 1;
    const float* x = g_xm + (size_t)row * 512;
    const float* w = Wc + j * 512;
    float s = 0.f;
    for (int k = 0; k < 512; k++) s += x[k] * w[k];
    g_outs[row * 2 + j] = s + bc[j];
}

// ---------------- segment mean + final scatter ----------------
__global__ void zero_seg_kernel() {
    int t = threadIdx.x;
    if (t < kB * 17 * 3) g_sums[t] = 0.f;
    if (t < kB * 17) g_cnt[t] = 0.f;
}

__global__ void seg_kernel(const float* __restrict__ probs, const int* __restrict__ masks) {
    __shared__ float ssum[51];
    __shared__ float scnt[17];
    int t = threadIdx.x;
    if (t < 51) ssum[t] = 0.f;
    if (t < 17) scnt[t] = 0.f;
    __syncthreads();
    int b = blockIdx.x >> 6;
    int chunk = blockIdx.x & 63;
    int base = chunk * 1024;
#pragma unroll
    for (int k = 0; k < 4; k++) {
        int pix = base + k * 256 + t;
        int lab = masks[b * 65536 + pix];
        atomicAdd(&scnt[lab], 1.f);
#pragma unroll
        for (int c = 0; c < 3; c++)
            atomicAdd(&ssum[lab * 3 + c], probs[((size_t)(b * 3 + c)) * 65536 + pix]);
    }
    __syncthreads();
    if (t < 51) atomicAdd(&g_sums[b * 51 + t], ssum[t]);
    if (t < 17) atomicAdd(&g_cnt[b * 17 + t], scnt[t]);
}

__global__ void newv_kernel() {
    int t = threadIdx.x;
    if (t < 24) { int b = t / 3, c = t % 3; g_newv[b * 51 + c] = 0.f; }
    int b = t >> 4, p = t & 15, lab = p + 1;
    float denom = fmaxf(g_cnt[b * 17 + lab], 1.f);
    float m0 = g_sums[(b * 17 + lab) * 3 + 0] / denom + 1e-6f;
    float m1 = g_sums[(b * 17 + lab) * 3 + 1] / denom + 1e-6f;
    float m2 = g_sums[(b * 17 + lab) * 3 + 2] / denom + 1e-6f;
    float o0 = g_outs[(b * 16 + p) * 2 + 0], o1 = g_outs[(b * 16 + p) * 2 + 1];
    float n0 = m0 / (0.5f * (m1 + m2)) * (0.5f * (o0 + o1));
    g_newv[(b * 17 + lab) * 3 + 0] = n0;
    g_newv[(b * 17 + lab) * 3 + 1] = o0;
    g_newv[(b * 17 + lab) * 3 + 2] = o1;
}

__global__ void scatter_kernel(const float* __restrict__ probs, const int* __restrict__ masks,
                               float* __restrict__ out) {
    int i = blockIdx.x * blockDim.x + threadIdx.x;
    if (i >= kB * 65536) return;
    int b = i >> 16, pix = i & 65535;
    int lab = masks[i];
#pragma unroll
    for (int c = 0; c < 3; c++) {
        size_t o = ((size_t)(b * 3 + c)) * 65536 + pix;
        out[o] = (lab > 0) ? g_newv[(b * 17 + lab) * 3 + c] : probs[o];
    }
}

// ---------------- launch ----------------
extern "C" void kernel_launch(void* const* d_in, const int* /*in_sizes*/, int /*n_in*/,
                              void* d_out, int /*out_size*/) {
    const float* features = (const float*)d_in[0];
    const float* probs    = (const float*)d_in[1];
    const float* patches  = (const float*)d_in[2];
    const int*   masks    = (const int*)d_in[3];
    const float* ln_g = (const float*)d_in[4];
    const float* ln_b = (const float*)d_in[5];
    const float* Wr   = (const float*)d_in[6];
    const float* br   = (const float*)d_in[7];
    const float* Wqkv = (const float*)d_in[8];
    const float* bqkv = (const float*)d_in[9];
    const float* Wo   = (const float*)d_in[10];
    const float* bo   = (const float*)d_in[11];
    const float* Wm   = (const float*)d_in[12];
    const float* bm   = (const float*)d_in[13];
    const float* Wc   = (const float*)d_in[14];
    const float* bc   = (const float*)d_in[15];
    float* out = (float*)d_out;

    cudaFuncSetAttribute(gemm_bf16_kernel, cudaFuncAttributeMaxDynamicSharedMemorySize,
                         GEMM_SMEM_BYTES);
    cudaFuncSetAttribute(attn_kernel, cudaFuncAttributeMaxDynamicSharedMemorySize,
                         ATT_SMEM_BYTES);

    uint32_t *pXp0, *pXp1, *pWrp0, *pWrp1, *pWqkvp0, *pWqkvp1, *pWop0, *pWop1, *pWmp0, *pWmp1;
    uint32_t *pYnp0, *pYnp1, *pAttnp0, *pAttnp1, *pResp0, *pResp1;
    float *pY, *pY2, *pYn, *pQKV, *pProj, *pRes, *pHid;
    cudaGetSymbolAddress((void**)&pXp0, g_Xp0);
    cudaGetSymbolAddress((void**)&pXp1, g_Xp1);
    cudaGetSymbolAddress((void**)&pWrp0, g_Wrp0);
    cudaGetSymbolAddress((void**)&pWrp1, g_Wrp1);
    cudaGetSymbolAddress((void**)&pWqkvp0, g_Wqkvp0);
    cudaGetSymbolAddress((void**)&pWqkvp1, g_Wqkvp1);
    cudaGetSymbolAddress((void**)&pWop0, g_Wop0);
    cudaGetSymbolAddress((void**)&pWop1, g_Wop1);
    cudaGetSymbolAddress((void**)&pWmp0, g_Wmp0);
    cudaGetSymbolAddress((void**)&pWmp1, g_Wmp1);
    cudaGetSymbolAddress((void**)&pYnp0, g_Ynp0);
    cudaGetSymbolAddress((void**)&pYnp1, g_Ynp1);
    cudaGetSymbolAddress((void**)&pAttnp0, g_attnp0);
    cudaGetSymbolAddress((void**)&pAttnp1, g_attnp1);
    cudaGetSymbolAddress((void**)&pResp0, g_resp0);
    cudaGetSymbolAddress((void**)&pResp1, g_resp1);
    cudaGetSymbolAddress((void**)&pY, g_Y);
    cudaGetSymbolAddress((void**)&pY2, g_Y2);
    cudaGetSymbolAddress((void**)&pYn, g_Yn);
    cudaGetSymbolAddress((void**)&pQKV, g_QKV);
    cudaGetSymbolAddress((void**)&pProj, g_proj);
    cudaGetSymbolAddress((void**)&pRes, g_res);
    cudaGetSymbolAddress((void**)&pHid, g_hid);

    // producers: fused pooling+scatter for blocks; patches; batched weight splits
    pool_features_fused_kernel<<<(kB * 16 * 128 * 64) / 256, 256>>>(features);
    pool_patches_kernel<<<(kPatchRows * (kFV / 2)) / 256, 256>>>(patches);
    split_weight_kernel<<<(kE * kFV / 2) / 256, 256>>>(Wr, pWrp0, pWrp1, kE * kFV / 2);
    split_weight3_kernel<<<(5 * kE * kE / 2) / 256, 256>>>(
        Wqkv, Wo, Wm, pWqkvp0, pWqkvp1, pWop0, pWop1, pWmp0, pWmp1);

    // patch2vec: split-K=2 in ONE launch (gridDim.z), summed inside next LN
    constexpr int K2full = kFV / 2;    // 2048
    constexpr int K2half = K2full / 2; // 1024
    gemm_bf16_kernel<<<dim3(512 / 64, (kRows + 127) / 128, 2), 256, GEMM_SMEM_BYTES>>>(
        pXp0, pXp1, pWrp0, pWrp1, br, pY, pY2, kRows, 512, K2half, K2full);
    ln_kernel<<<kRows, 256>>>(pY, pY2, ln_g, ln_b, pYn, pYnp0, pYnp1);

    // fused QKV: (1928,512)@(512,1536)^T
    gemm_bf16_kernel<<<dim3(1536 / 64, (kRows + 127) / 128, 1), 256, GEMM_SMEM_BYTES>>>(
        pYnp0, pYnp1, pWqkvp0, pWqkvp1, bqkv, pQKV, nullptr, kRows, 1536, kE / 2, kE / 2);
    attn_kernel<<<kB * kNH, 256, ATT_SMEM_BYTES>>>();

    // out proj + residual LN
    gemm_bf16_kernel<<<dim3(512 / 64, 1, 1), 256, GEMM_SMEM_BYTES>>>(
        pAttnp0, pAttnp1, pWop0, pWop1, bo, pProj, nullptr, kPatchRows, 512, kE / 2, kE / 2);
    ln_kernel<<<kPatchRows, 256>>>(pProj, pYn, ln_g, ln_b, pRes, pResp0, pResp1);

    // MLP
    gemm_bf16_kernel<<<dim3(512 / 64, 1, 1), 256, GEMM_SMEM_BYTES>>>(
        pResp0, pResp1, pWmp0, pWmp1, bm, pHid, nullptr, kPatchRows, 512, kE / 2, kE / 2);
    gelu_res_kernel<<<(kPatchRows * kE) / 256, 256>>>();
    outs_kernel<<<1, 256>>>(Wc, bc);

    // segment statistics + final output
    zero_seg_kernel<<<1, 512>>>();
    seg_kernel<<<kB * 64, 256>>>(probs, masks);
    newv_kernel<<<1, 128>>>();
    scatter_kernel<<<(kB * 65536) / 256, 256>>>(probs, masks, out);
}

// round 9
// speedup vs baseline: 3.0682x; 1.1142x over previous
#include <cuda_runtime.h>
#include <cuda_bf16.h>
#include <math.h>
#include <stdint.h>

// ---------------- problem constants ----------------
constexpr int kB = 8, kC = 64, kH = 256, kW = 256;
constexpr int kE = 512, kNH = 8, kHD = 64;
constexpr int kP = 16, kN = 15, kL = 225;      // n=15 windows, L=225 blocks/img
constexpr int kFV = 4096;                       // 16 ch-groups * 16 * 16
constexpr int kRows = kB * (kP + kL);           // 1928 rows
constexpr int kPatchRows = kB * kP;             // 128

// ---------------- device scratch ----------------
__device__ uint32_t g_Xp0[kRows * (kFV / 2)];
__device__ uint32_t g_Xp1[kRows * (kFV / 2)];
__device__ uint32_t g_Wrp0[kE * (kFV / 2)], g_Wrp1[kE * (kFV / 2)];
__device__ uint32_t g_Wqkvp0[3 * kE * (kE / 2)], g_Wqkvp1[3 * kE * (kE / 2)];
__device__ uint32_t g_Wop0[kE * (kE / 2)], g_Wop1[kE * (kE / 2)];
__device__ uint32_t g_Wmp0[kE * (kE / 2)], g_Wmp1[kE * (kE / 2)];
__device__ uint32_t g_Ynp0[kRows * (kE / 2)], g_Ynp1[kRows * (kE / 2)];
__device__ uint32_t g_attnp0[kPatchRows * (kE / 2)], g_attnp1[kPatchRows * (kE / 2)];
__device__ uint32_t g_resp0[kPatchRows * (kE / 2)], g_resp1[kPatchRows * (kE / 2)];

__device__ float g_Y[kRows * kE];
__device__ float g_Y2[kRows * kE];
__device__ float g_Yn[kRows * kE];
__device__ float g_QKV[kRows * 3 * kE];
__device__ float g_proj[kPatchRows * kE];
__device__ float g_res[kPatchRows * kE];
__device__ float g_hid[kPatchRows * kE];
__device__ float g_xm[kPatchRows * kE];
__device__ float g_outs[kPatchRows * 2];
__device__ float g_sums[kB * 17 * 3];
__device__ float g_cnt[kB * 17];
__device__ float g_newv[kB * 17 * 3];

// ---------------- bf16 split/pack ----------------
__device__ __forceinline__ void pack_pair(float x0, float x1, uint32_t& w0, uint32_t& w1) {
    __nv_bfloat162 h = __floats2bfloat162_rn(x0, x1);
    float r0 = x0 - __low2float(h);
    float r1 = x1 - __high2float(h);
    __nv_bfloat162 l = __floats2bfloat162_rn(r0, r1);
    w0 = *reinterpret_cast<uint32_t*>(&h);
    w1 = *reinterpret_cast<uint32_t*>(&l);
}

// ---------------- fused pooling + window scatter ----------------
__global__ void pool_features_fused_kernel(const float* __restrict__ f) {
    int i = blockIdx.x * blockDim.x + threadIdx.x;
    if (i >= kB * 16 * 128 * 64) return;
    int xp = i & 63, y = (i >> 6) & 127, cg = (i >> 13) & 15, b = i >> 17;
    float s0 = 0.f, s1 = 0.f;
#pragma unroll
    for (int cc = 0; cc < 4; cc++) {
        const float* base = f + ((size_t)(b * kC + cg * 4 + cc) * kH + 2 * y) * kW + 4 * xp;
#pragma unroll
        for (int dy = 0; dy < 2; dy++) {
            float4 q = *(const float4*)(base + dy * kW);
            s0 += q.x + q.y;
            s1 += q.z + q.w;
        }
    }
    uint32_t w0, w1;
    pack_pair(s0 * (1.f / 16.f), s1 * (1.f / 16.f), w0, w1);
#pragma unroll
    for (int dli = 0; dli < 2; dli++) {
        int li = (y >> 3) - dli;
        if (li < 0 || li > 14) continue;
        int hh = y - 8 * li;
#pragma unroll
        for (int dlj = 0; dlj < 2; dlj++) {
            int lj = (xp >> 2) - dlj;
            if (lj < 0 || lj > 14) continue;
            int w2 = xp - 4 * lj;
            size_t idx = (size_t)(kPatchRows + b * kL + li * kN + lj) * 2048 +
                         cg * 128 + hh * 8 + w2;
            g_Xp0[idx] = w0;
            g_Xp1[idx] = w1;
        }
    }
}

__global__ void pool_patches_kernel(const float* __restrict__ p) {
    int i = blockIdx.x * blockDim.x + threadIdx.x;
    if (i >= kPatchRows * (kFV / 2)) return;
    int v2 = i & 2047, n = i >> 11;
    int w2 = v2 & 7, hh = (v2 >> 3) & 15, cg = v2 >> 7;
    float s0 = 0.f, s1 = 0.f;
#pragma unroll
    for (int cc = 0; cc < 4; cc++) {
        const float* base = p + (size_t)n * 65536 + (cg * 4 + cc) * 1024 + 4 * w2;
#pragma unroll
        for (int dh = 0; dh < 2; dh++) {
            float4 q = *(const float4*)(base + (2 * hh + dh) * 32);
            s0 += q.x + q.y;
            s1 += q.z + q.w;
        }
    }
    uint32_t w0, w1;
    pack_pair(s0 * (1.f / 16.f), s1 * (1.f / 16.f), w0, w1);
    g_Xp0[(size_t)n * 2048 + v2] = w0;
    g_Xp1[(size_t)n * 2048 + v2] = w1;
}

// one kernel splits all four weight matrices
__global__ void split_all_kernel(const float* __restrict__ Wr, const float* __restrict__ Wqkv,
                                 const float* __restrict__ Wo, const float* __restrict__ Wm) {
    const int n0 = kE * kFV / 2, n1 = 3 * kE * kE / 2, n2 = kE * kE / 2;
    int i = blockIdx.x * blockDim.x + threadIdx.x;
    const float* W;
    uint32_t *P0, *P1;
    int j;
    if (i < n0) { W = Wr; P0 = g_Wrp0; P1 = g_Wrp1; j = i; }
    else if (i < n0 + n1) { W = Wqkv; P0 = g_Wqkvp0; P1 = g_Wqkvp1; j = i - n0; }
    else if (i < n0 + n1 + n2) { W = Wo; P0 = g_Wop0; P1 = g_Wop1; j = i - n0 - n1; }
    else if (i < n0 + n1 + 2 * n2) { W = Wm; P0 = g_Wmp0; P1 = g_Wmp1; j = i - n0 - n1 - n2; }
    else return;
    float2 x = *(const float2*)&W[2 * j];
    uint32_t w0, w1;
    pack_pair(x.x, x.y, w0, w1);
    P0[j] = w0;
    P1[j] = w1;
}

// ---------------- bf16x2 (3-mma) tensor GEMM, BK=64 elements ----------------
__device__ __forceinline__ void mma_bf16(float* d, const uint32_t* a, const uint32_t* b) {
    asm volatile(
        "mma.sync.aligned.m16n8k16.row.col.f32.bf16.bf16.f32 "
        "{%0,%1,%2,%3}, {%4,%5,%6,%7}, {%8,%9}, {%0,%1,%2,%3};"
        : "+f"(d[0]), "+f"(d[1]), "+f"(d[2]), "+f"(d[3])
        : "r"(a[0]), "r"(a[1]), "r"(a[2]), "r"(a[3]), "r"(b[0]), "r"(b[1]));
}

__device__ __forceinline__ void cp_async16(void* smem, const void* g, bool valid) {
    uint32_t s = (uint32_t)__cvta_generic_to_shared(smem);
    int sz = valid ? 16 : 0;
    asm volatile("cp.async.cg.shared.global [%0], [%1], 16, %2;\n" :: "r"(s), "l"(g), "r"(sz));
}
__device__ __forceinline__ void cp_commit() { asm volatile("cp.async.commit_group;" ::: "memory"); }
template <int NN>
__device__ __forceinline__ void cp_wait() { asm volatile("cp.async.wait_group %0;" :: "n"(NN)); }

// Row = 32 data words + 4 pad = 36 words (144B: 16B-aligned for cp.async).
// Fragment LDS bank = (36*g + t4) mod 32 = (4g + t4) mod 32: all distinct.
constexpr int GPAD = 36;
constexpr int GEMM_SMEM_BYTES = (2 * 128 * GPAD * 2 + 2 * 64 * GPAD * 2) * 4;  // 110,592

__global__ __launch_bounds__(256) void gemm_bf16_kernel(
    const uint32_t* __restrict__ A0, const uint32_t* __restrict__ A1,
    const uint32_t* __restrict__ B0, const uint32_t* __restrict__ B1,
    const float* __restrict__ bias, float* __restrict__ Cm, float* __restrict__ Cm2,
    int M, int N, int K2len, int K2s)
{
    if (blockIdx.z == 1) {
        A0 += K2len; A1 += K2len; B0 += K2len; B1 += K2len;
        Cm = Cm2;
        bias = nullptr;
    }
    extern __shared__ uint32_t sm[];
    uint32_t* As0 = sm;                       // [2][128][GPAD]
    uint32_t* As1 = As0 + 2 * 128 * GPAD;
    uint32_t* Bs0 = As1 + 2 * 128 * GPAD;     // [2][64][GPAD]
    uint32_t* Bs1 = Bs0 + 2 * 64 * GPAD;

    const int tid = threadIdx.x;
    const int lane = tid & 31, wid = tid >> 5;
    const int wm = wid >> 1, wn = wid & 1;
    const int g = lane >> 2, t4 = lane & 3;
    const int m0 = blockIdx.y * 128, n0 = blockIdx.x * 64;

    float acc[2][4][4];
#pragma unroll
    for (int mt = 0; mt < 2; mt++)
#pragma unroll
        for (int nt = 0; nt < 4; nt++)
#pragma unroll
            for (int i = 0; i < 4; i++) acc[mt][nt][i] = 0.f;

    auto load_stage = [&](int buf, int kt) {
        int k0 = kt * 32;
#pragma unroll
        for (int i = 0; i < 4; i++) {
            int idx = tid + i * 256;
            int row = idx >> 3, c4 = (idx & 7) * 4;
            bool v = (m0 + row) < M;
            size_t off = (size_t)(v ? (m0 + row) : 0) * K2s + k0 + c4;
            cp_async16(&As0[(buf * 128 + row) * GPAD + c4], A0 + off, v);
            cp_async16(&As1[(buf * 128 + row) * GPAD + c4], A1 + off, v);
        }
#pragma unroll
        for (int i = 0; i < 2; i++) {
            int idx = tid + i * 256;
            int row = idx >> 3, c4 = (idx & 7) * 4;
            size_t off = (size_t)(n0 + row) * K2s + k0 + c4;
            cp_async16(&Bs0[(buf * 64 + row) * GPAD + c4], B0 + off, true);
            cp_async16(&Bs1[(buf * 64 + row) * GPAD + c4], B1 + off, true);
        }
        cp_commit();
    };

    auto compute = [&](int buf) {
#pragma unroll
        for (int sl = 0; sl < 4; sl++) {
            int ks = sl * 8;
            uint32_t a0[2][4], a1[2][4], b0[4][2], b1[4][2];
#pragma unroll
            for (int mt = 0; mt < 2; mt++) {
                int mr = buf * 128 + wm * 32 + mt * 16;
                a0[mt][0] = As0[(mr + g) * GPAD + ks + t4];
                a0[mt][1] = As0[(mr + g + 8) * GPAD + ks + t4];
                a0[mt][2] = As0[(mr + g) * GPAD + ks + t4 + 4];
                a0[mt][3] = As0[(mr + g + 8) * GPAD + ks + t4 + 4];
                a1[mt][0] = As1[(mr + g) * GPAD + ks + t4];
                a1[mt][1] = As1[(mr + g + 8) * GPAD + ks + t4];
                a1[mt][2] = As1[(mr + g) * GPAD + ks + t4 + 4];
                a1[mt][3] = As1[(mr + g + 8) * GPAD + ks + t4 + 4];
            }
#pragma unroll
            for (int nt = 0; nt < 4; nt++) {
                int nr = buf * 64 + wn * 32 + nt * 8 + g;
                b0[nt][0] = Bs0[nr * GPAD + ks + t4];
                b0[nt][1] = Bs0[nr * GPAD + ks + t4 + 4];
                b1[nt][0] = Bs1[nr * GPAD + ks + t4];
                b1[nt][1] = Bs1[nr * GPAD + ks + t4 + 4];
            }
#pragma unroll
            for (int mt = 0; mt < 2; mt++)
#pragma unroll
                for (int nt = 0; nt < 4; nt++) {
                    mma_bf16(acc[mt][nt], a0[mt], b0[nt]);
                    mma_bf16(acc[mt][nt], a0[mt], b1[nt]);
                    mma_bf16(acc[mt][nt], a1[mt], b0[nt]);
                }
        }
    };

    const int kTiles = K2len / 32;
    load_stage(0, 0);
    int buf = 0;
    for (int kt = 0; kt < kTiles; kt++) {
        if (kt + 1 < kTiles) {
            load_stage(buf ^ 1, kt + 1);
            cp_wait<1>();
        } else {
            cp_wait<0>();
        }
        __syncthreads();
        compute(buf);
        __syncthreads();
        buf ^= 1;
    }

#pragma unroll
    for (int mt = 0; mt < 2; mt++) {
#pragma unroll
        for (int nt = 0; nt < 4; nt++) {
            int gc = n0 + wn * 32 + nt * 8 + t4 * 2;
            float b0v = bias ? bias[gc] : 0.f;
            float b1v = bias ? bias[gc + 1] : 0.f;
            int gr0 = m0 + wm * 32 + mt * 16 + g;
            if (gr0 < M) {
                float2 o = make_float2(acc[mt][nt][0] + b0v, acc[mt][nt][1] + b1v);
                *(float2*)(Cm + (size_t)gr0 * N + gc) = o;
            }
            int gr1 = gr0 + 8;
            if (gr1 < M) {
                float2 o = make_float2(acc[mt][nt][2] + b0v, acc[mt][nt][3] + b1v);
                *(float2*)(Cm + (size_t)gr1 * N + gc) = o;
            }
        }
    }
}

// ---------------- layernorm: warp-per-row, shuffle-only ----------------
__global__ __launch_bounds__(256) void ln_kernel(
    const float* __restrict__ in, const float* __restrict__ resid,
    const float* __restrict__ g, const float* __restrict__ bb,
    float* __restrict__ out, uint32_t* __restrict__ p0, uint32_t* __restrict__ p1) {
    int warp = threadIdx.x >> 5, lane = threadIdx.x & 31;
    int row = blockIdx.x * 8 + warp;
    size_t base = (size_t)row * 512;
    float4 x[4];
    float sum = 0.f;
#pragma unroll
    for (int k = 0; k < 4; k++) {
        int idx = lane * 4 + k * 128;
        x[k] = *(const float4*)&in[base + idx];
        if (resid) {
            float4 r = *(const float4*)&resid[base + idx];
            x[k].x += r.x; x[k].y += r.y; x[k].z += r.z; x[k].w += r.w;
        }
        sum += x[k].x + x[k].y + x[k].z + x[k].w;
    }
#pragma unroll
    for (int o = 16; o; o >>= 1) sum += __shfl_xor_sync(0xffffffffu, sum, o);
    float mu = sum * (1.f / 512.f);
    float var = 0.f;
#pragma unroll
    for (int k = 0; k < 4; k++) {
        x[k].x -= mu; x[k].y -= mu; x[k].z -= mu; x[k].w -= mu;
        var += x[k].x * x[k].x + x[k].y * x[k].y + x[k].z * x[k].z + x[k].w * x[k].w;
    }
#pragma unroll
    for (int o = 16; o; o >>= 1) var += __shfl_xor_sync(0xffffffffu, var, o);
    float rstd = rsqrtf(var * (1.f / 512.f) + 1e-5f);
#pragma unroll
    for (int k = 0; k < 4; k++) {
        int idx = lane * 4 + k * 128;
        float4 gv = *(const float4*)&g[idx];
        float4 bv = *(const float4*)&bb[idx];
        float4 y;
        y.x = x[k].x * rstd * gv.x + bv.x;
        y.y = x[k].y * rstd * gv.y + bv.y;
        y.z = x[k].z * rstd * gv.z + bv.z;
        y.w = x[k].w * rstd * gv.w + bv.w;
        *(float4*)&out[base + idx] = y;
        uint32_t w0, w1, w2, w3;
        pack_pair(y.x, y.y, w0, w1);
        pack_pair(y.z, y.w, w2, w3);
        size_t pi = (size_t)row * 256 + lane * 2 + k * 64;
        p0[pi] = w0; p0[pi + 1] = w2;
        p1[pi] = w1; p1[pi + 1] = w3;
    }
}

// ---------------- attention: smem-staged K/V ----------------
constexpr int ATT_KS = 64 * 229;
constexpr int ATT_VS = 225 * 68;
constexpr int ATT_QS = 16 * 64;
constexpr int ATT_SC = 16 * 228;
constexpr int ATT_SMEM_BYTES = (ATT_KS + ATT_VS + ATT_QS + ATT_SC) * 4;

__global__ __launch_bounds__(256) void attn_kernel() {
    extern __shared__ float smf[];
    float* Ks = smf;
    float* Vs = Ks + ATT_KS;
    float* qs = Vs + ATT_VS;
    float* sc = qs + ATT_QS;
    int bh = blockIdx.x;
    int b = bh >> 3, h = bh & 7;
    int tid = threadIdx.x;

    for (int i = tid; i < 1024; i += 256)
        qs[i] = g_QKV[(size_t)(b * 16 + (i >> 6)) * 1536 + h * 64 + (i & 63)];
    for (int i = tid; i < 225 * 64; i += 256) {
        int l = i >> 6, d = i & 63;
        const float* row = g_QKV + (size_t)(kPatchRows + b * kL + l) * 1536 + h * 64 + d;
        Ks[d * 229 + l] = row[512];
        Vs[l * 68 + d] = row[1024];
    }
    __syncthreads();

    for (int idx = tid; idx < 16 * 225; idx += 256) {
        int p = idx / 225, l = idx - p * 225;
        float s = 0.f;
#pragma unroll
        for (int d = 0; d < 64; d++) s += qs[p * 64 + d] * Ks[d * 229 + l];
        sc[p * 228 + l] = s * 0.125f;
    }
    __syncthreads();

    int warp = tid >> 5, lane = tid & 31;
    for (int p = warp; p < 16; p += 8) {
        float mx = -1e30f;
        for (int l = lane; l < 225; l += 32) mx = fmaxf(mx, sc[p * 228 + l]);
#pragma unroll
        for (int o = 16; o; o >>= 1) mx = fmaxf(mx, __shfl_xor_sync(0xffffffffu, mx, o));
        float sum = 0.f;
        for (int l = lane; l < 225; l += 32) {
            float e = __expf(sc[p * 228 + l] - mx);
            sc[p * 228 + l] = e;
            sum += e;
        }
#pragma unroll
        for (int o = 16; o; o >>= 1) sum += __shfl_xor_sync(0xffffffffu, sum, o);
        float inv = 1.f / sum;
        for (int l = lane; l < 225; l += 32) sc[p * 228 + l] *= inv;
    }
    __syncthreads();

    for (int i = tid; i < 512; i += 256) {
        int p = i >> 5, d2 = i & 31;
        float s0 = 0.f, s1 = 0.f;
        const float* sp = sc + p * 228;
        const float* vp = Vs + 2 * d2;
        for (int l = 0; l < 225; l++) {
            float2 v = *(const float2*)(vp + l * 68);
            float w = sp[l];
            s0 += w * v.x;
            s1 += w * v.y;
        }
        uint32_t w0, w1;
        pack_pair(s0, s1, w0, w1);
        size_t oi = (size_t)(b * 16 + p) * 256 + h * 32 + d2;
        g_attnp0[oi] = w0;
        g_attnp1[oi] = w1;
    }
}

// ---------------- MLP epilogue ----------------
__global__ void gelu_res_kernel() {
    int i = blockIdx.x * blockDim.x + threadIdx.x;
    if (i >= kPatchRows * kE) return;
    float hv = g_hid[i];
    g_xm[i] = 0.5f * hv * (1.f + erff(hv * 0.70710678118654752f)) + g_res[i];
}

// fused: outs (128x2 dot products) then newv (needs g_sums/g_cnt from seg)
__global__ void outs_newv_kernel(const float* __restrict__ Wc, const float* __restrict__ bc) {
    __shared__ float s_outs[256];
    int t = threadIdx.x;  // 256
    {
        int row = t >> 1, j = t & 1;
        const float* x = g_xm + (size_t)row * 512;
        const float* w = Wc + j * 512;
        float s = 0.f;
        for (int k = 0; k < 512; k++) s += x[k] * w[k];
        s_outs[t] = s + bc[j];
    }
    __syncthreads();
    if (t < 128) {
        if (t < 24) { int b = t / 3, c = t % 3; g_newv[b * 51 + c] = 0.f; }
        int b = t >> 4, p = t & 15, lab = p + 1;
        float denom = fmaxf(g_cnt[b * 17 + lab], 1.f);
        float m0 = g_sums[(b * 17 + lab) * 3 + 0] / denom + 1e-6f;
        float m1 = g_sums[(b * 17 + lab) * 3 + 1] / denom + 1e-6f;
        float m2 = g_sums[(b * 17 + lab) * 3 + 2] / denom + 1e-6f;
        float o0 = s_outs[2 * t], o1 = s_outs[2 * t + 1];
        float n0 = m0 / (0.5f * (m1 + m2)) * (0.5f * (o0 + o1));
        g_newv[(b * 17 + lab) * 3 + 0] = n0;
        g_newv[(b * 17 + lab) * 3 + 1] = o0;
        g_newv[(b * 17 + lab) * 3 + 2] = o1;
    }
}

// ---------------- segment mean + final scatter ----------------
__global__ void zero_seg_kernel() {
    int t = threadIdx.x;
    if (t < kB * 17 * 3) g_sums[t] = 0.f;
    if (t < kB * 17) g_cnt[t] = 0.f;
}

__global__ void seg_kernel(const float* __restrict__ probs, const int* __restrict__ masks) {
    __shared__ float ssum[51];
    __shared__ float scnt[17];
    int t = threadIdx.x;
    if (t < 51) ssum[t] = 0.f;
    if (t < 17) scnt[t] = 0.f;
    __syncthreads();
    int b = blockIdx.x >> 6;
    int chunk = blockIdx.x & 63;
    int base = chunk * 1024;
#pragma unroll
    for (int k = 0; k < 4; k++) {
        int pix = base + k * 256 + t;
        int lab = masks[b * 65536 + pix];
        atomicAdd(&scnt[lab], 1.f);
#pragma unroll
        for (int c = 0; c < 3; c++)
            atomicAdd(&ssum[lab * 3 + c], probs[((size_t)(b * 3 + c)) * 65536 + pix]);
    }
    __syncthreads();
    if (t < 51) atomicAdd(&g_sums[b * 51 + t], ssum[t]);
    if (t < 17) atomicAdd(&g_cnt[b * 17 + t], scnt[t]);
}

__global__ void scatter_kernel(const float* __restrict__ probs, const int* __restrict__ masks,
                               float* __restrict__ out) {
    int i = blockIdx.x * blockDim.x + threadIdx.x;
    if (i >= kB * 65536) return;
    int b = i >> 16, pix = i & 65535;
    int lab = masks[i];
#pragma unroll
    for (int c = 0; c < 3; c++) {
        size_t o = ((size_t)(b * 3 + c)) * 65536 + pix;
        out[o] = (lab > 0) ? g_newv[(b * 17 + lab) * 3 + c] : probs[o];
    }
}

// ---------------- launch ----------------
extern "C" void kernel_launch(void* const* d_in, const int* /*in_sizes*/, int /*n_in*/,
                              void* d_out, int /*out_size*/) {
    const float* features = (const float*)d_in[0];
    const float* probs    = (const float*)d_in[1];
    const float* patches  = (const float*)d_in[2];
    const int*   masks    = (const int*)d_in[3];
    const float* ln_g = (const float*)d_in[4];
    const float* ln_b = (const float*)d_in[5];
    const float* Wr   = (const float*)d_in[6];
    const float* br   = (const float*)d_in[7];
    const float* Wqkv = (const float*)d_in[8];
    const float* bqkv = (const float*)d_in[9];
    const float* Wo   = (const float*)d_in[10];
    const float* bo   = (const float*)d_in[11];
    const float* Wm   = (const float*)d_in[12];
    const float* bm   = (const float*)d_in[13];
    const float* Wc   = (const float*)d_in[14];
    const float* bc   = (const float*)d_in[15];
    float* out = (float*)d_out;

    cudaFuncSetAttribute(gemm_bf16_kernel, cudaFuncAttributeMaxDynamicSharedMemorySize,
                         GEMM_SMEM_BYTES);
    cudaFuncSetAttribute(attn_kernel, cudaFuncAttributeMaxDynamicSharedMemorySize,
                         ATT_SMEM_BYTES);

    uint32_t *pXp0, *pXp1, *pWrp0, *pWrp1, *pWqkvp0, *pWqkvp1, *pWop0, *pWop1, *pWmp0, *pWmp1;
    uint32_t *pYnp0, *pYnp1, *pAttnp0, *pAttnp1, *pResp0, *pResp1;
    float *pY, *pY2, *pYn, *pQKV, *pProj, *pRes, *pHid;
    cudaGetSymbolAddress((void**)&pXp0, g_Xp0);
    cudaGetSymbolAddress((void**)&pXp1, g_Xp1);
    cudaGetSymbolAddress((void**)&pWrp0, g_Wrp0);
    cudaGetSymbolAddress((void**)&pWrp1, g_Wrp1);
    cudaGetSymbolAddress((void**)&pWqkvp0, g_Wqkvp0);
    cudaGetSymbolAddress((void**)&pWqkvp1, g_Wqkvp1);
    cudaGetSymbolAddress((void**)&pWop0, g_Wop0);
    cudaGetSymbolAddress((void**)&pWop1, g_Wop1);
    cudaGetSymbolAddress((void**)&pWmp0, g_Wmp0);
    cudaGetSymbolAddress((void**)&pWmp1, g_Wmp1);
    cudaGetSymbolAddress((void**)&pYnp0, g_Ynp0);
    cudaGetSymbolAddress((void**)&pYnp1, g_Ynp1);
    cudaGetSymbolAddress((void**)&pAttnp0, g_attnp0);
    cudaGetSymbolAddress((void**)&pAttnp1, g_attnp1);
    cudaGetSymbolAddress((void**)&pResp0, g_resp0);
    cudaGetSymbolAddress((void**)&pResp1, g_resp1);
    cudaGetSymbolAddress((void**)&pY, g_Y);
    cudaGetSymbolAddress((void**)&pY2, g_Y2);
    cudaGetSymbolAddress((void**)&pYn, g_Yn);
    cudaGetSymbolAddress((void**)&pQKV, g_QKV);
    cudaGetSymbolAddress((void**)&pProj, g_proj);
    cudaGetSymbolAddress((void**)&pRes, g_res);
    cudaGetSymbolAddress((void**)&pHid, g_hid);

    // producers
    pool_features_fused_kernel<<<(kB * 16 * 128 * 64) / 256, 256>>>(features);
    pool_patches_kernel<<<(kPatchRows * (kFV / 2)) / 256, 256>>>(patches);
    {
        int total = kE * kFV / 2 + 5 * kE * kE / 2;
        split_all_kernel<<<(total + 255) / 256, 256>>>(Wr, Wqkv, Wo, Wm);
    }

    // patch2vec: split-K=2 in one launch; summed in next LN
    constexpr int K2full = kFV / 2;    // 2048
    constexpr int K2half = K2full / 2; // 1024
    gemm_bf16_kernel<<<dim3(512 / 64, (kRows + 127) / 128, 2), 256, GEMM_SMEM_BYTES>>>(
        pXp0, pXp1, pWrp0, pWrp1, br, pY, pY2, kRows, 512, K2half, K2full);
    ln_kernel<<<kRows / 8, 256>>>(pY, pY2, ln_g, ln_b, pYn, pYnp0, pYnp1);

    // fused QKV
    gemm_bf16_kernel<<<dim3(1536 / 64, (kRows + 127) / 128, 1), 256, GEMM_SMEM_BYTES>>>(
        pYnp0, pYnp1, pWqkvp0, pWqkvp1, bqkv, pQKV, nullptr, kRows, 1536, kE / 2, kE / 2);
    attn_kernel<<<kB * kNH, 256, ATT_SMEM_BYTES>>>();

    // out proj + residual LN
    gemm_bf16_kernel<<<dim3(512 / 64, 1, 1), 256, GEMM_SMEM_BYTES>>>(
        pAttnp0, pAttnp1, pWop0, pWop1, bo, pProj, nullptr, kPatchRows, 512, kE / 2, kE / 2);
    ln_kernel<<<kPatchRows / 8, 256>>>(pProj, pYn, ln_g, ln_b, pRes, pResp0, pResp1);

    // MLP
    gemm_bf16_kernel<<<dim3(512 / 64, 1, 1), 256, GEMM_SMEM_BYTES>>>(
        pResp0, pResp1, pWmp0, pWmp1, bm, pHid, nullptr, kPatchRows, 512, kE / 2, kE / 2);
    gelu_res_kernel<<<(kPatchRows * kE) / 256, 256>>>();

    // segment statistics, then fused outs+newv, then final scatter
    zero_seg_kernel<<<1, 512>>>();
    seg_kernel<<<kB * 64, 256>>>(probs, masks);
    outs_newv_kernel<<<1, 256>>>(Wc, bc);
    scatter_kernel<<<(kB * 65536) / 256, 256>>>(probs, masks, out);
}